// round 12
// baseline (speedup 1.0000x reference)
#include <cuda_runtime.h>
#include <cuda_bf16.h>
#include <cstdint>

#define NB   64
#define CC   64
#define TT   256
#define VV   25

typedef unsigned long long ull;

// ---------------- scratch (static device memory) ----------------
__device__ __align__(16) __nv_bfloat16 g_W9b[9 * 128 * 64];  // [tap][ch][cin]
__device__ __align__(16) __nv_bfloat16 g_W1b[160 * 64];      // [ch][cin]
__device__ float g_b9[128];
__device__ float g_b1[160];
__device__ float g_Acomb[625];
__device__ float g_Gram[64 * 9 * 625];
__device__ float g_A1[64 * 3 * 625];
// tf32 A-fragments of WdS^stacked [192 x 64]: [12 strip][8 kt][32 lane][4]
__device__ __align__(16) float g_AfH[12288];
__device__ float g_bd2[64];

// branch tables
__constant__ int c_i9[8]  = {0,0,1,1,1,1,2,2};
__constant__ int c_s9[8]  = {0,1,0,1,2,3,0,1};
__constant__ int c_i1[10] = {0,0,0,0,1,1,2,2,2,2};
__constant__ int c_s1[10] = {0,1,2,3,0,1,0,1,2,3};
__constant__ int c_gi9[4] = {0,1,1,2};
__constant__ int c_gj9[4] = {1,1,2,1};
__constant__ int c_gi1[5] = {0,0,1,2,2};
__constant__ int c_gj1[5] = {0,2,0,0,2};

// ---------------- helpers ----------------
__device__ __forceinline__ ull pack2(float lo, float hi) {
    ull r; asm("mov.b64 %0, {%1,%2};" : "=l"(r) : "f"(lo), "f"(hi)); return r;
}
__device__ __forceinline__ void fma2(ull& d, ull a, ull b) {
    asm("fma.rn.f32x2 %0, %1, %2, %0;" : "+l"(d) : "l"(a), "l"(b));
}
__device__ __forceinline__ float2 unpack2(ull p) {
    float2 f; asm("mov.b64 {%0,%1}, %2;" : "=f"(f.x), "=f"(f.y) : "l"(p)); return f;
}
__device__ __forceinline__ float tf32r(float f) {
    uint32_t u;
    asm("cvt.rn.tf32.f32 %0, %1;" : "=r"(u) : "f"(f));
    return __uint_as_float(u);
}
__device__ __forceinline__ uint32_t smem_u32(const void* p) {
    uint32_t a;
    asm("{ .reg .u64 t; cvta.to.shared.u64 t, %1; cvt.u32.u64 %0, t; }" : "=r"(a) : "l"(p));
    return a;
}
__device__ __forceinline__ void ldsm4(uint32_t& r0, uint32_t& r1, uint32_t& r2,
                                      uint32_t& r3, uint32_t a) {
    asm volatile("ldmatrix.sync.aligned.m8n8.x4.shared.b16 {%0,%1,%2,%3}, [%4];"
                 : "=r"(r0), "=r"(r1), "=r"(r2), "=r"(r3) : "r"(a));
}
__device__ __forceinline__ void mma_bf16(float* d, uint32_t a0, uint32_t a1,
                                         uint32_t a2, uint32_t a3,
                                         uint32_t b0, uint32_t b1) {
    asm volatile(
        "mma.sync.aligned.m16n8k16.row.col.f32.bf16.bf16.f32 "
        "{%0,%1,%2,%3}, {%4,%5,%6,%7}, {%8,%9}, {%0,%1,%2,%3};"
        : "+f"(d[0]), "+f"(d[1]), "+f"(d[2]), "+f"(d[3])
        : "r"(a0), "r"(a1), "r"(a2), "r"(a3), "r"(b0), "r"(b1));
}
__device__ __forceinline__ void mma_tf32(float* d, float4 a, uint32_t b0, uint32_t b1) {
    asm volatile(
        "mma.sync.aligned.m16n8k8.row.col.f32.tf32.tf32.f32 "
        "{%0,%1,%2,%3}, {%4,%5,%6,%7}, {%8,%9}, {%0,%1,%2,%3};"
        : "+f"(d[0]), "+f"(d[1]), "+f"(d[2]), "+f"(d[3])
        : "r"(__float_as_uint(a.x)), "r"(__float_as_uint(a.y)),
          "r"(__float_as_uint(a.z)), "r"(__float_as_uint(a.w)),
          "r"(b0), "r"(b1));
}

// ---------------- kernel 0a: prepA ----------------
__global__ void prepA_kernel(const float* __restrict__ weights, const float* __restrict__ A,
                             const float* __restrict__ ba, const float* __restrict__ bb,
                             const float* __restrict__ bT1, const float* __restrict__ bT2,
                             const float* __restrict__ bST11, const float* __restrict__ bST12,
                             const float* __restrict__ bd,
                             const float* __restrict__ gamma, const float* __restrict__ beta,
                             const float* __restrict__ mean, const float* __restrict__ var) {
    __shared__ float sA[625], sA4[625];
    const int tid = threadIdx.x;
    if (tid < 625) {
        float a = A[tid];
        sA[tid] = a;
        int v = tid / 25, w = tid % 25;
        float a2 = a * a;  // elementwise Chebyshev (torch.pow semantics)
        sA4[tid] = 8.f * a2 * a2 - 8.f * a2 + (v == w ? 1.f : 0.f);
    }
    __syncthreads();
    if (tid < 25) {
        const int w = tid;
        float w0 = weights[0], w1 = weights[1];
        float m = -1e30f;
        for (int v = 0; v < 25; ++v) m = fmaxf(m, sA4[v*25+w] * 0.04f);
        float ssum = 0.f;
        for (int v = 0; v < 25; ++v) ssum += expf(sA4[v*25+w] * 0.04f - m);
        float inv = 1.f / ssum;
        for (int v = 0; v < 25; ++v)
            g_Acomb[v*25+w] = w0 * sA[v*25+w] + w1 * expf(sA4[v*25+w] * 0.04f - m) * inv;
    }
    for (int idx = tid; idx < 128; idx += blockDim.x) {
        int g = idx >> 4, c = idx & 15;
        int i = c_i9[g], s = c_s9[g];
        const float* B = (s == 0) ? bT1 : (s == 1) ? bT2 : (s == 2) ? bST11 : bST12;
        g_b9[idx] = B[i*16 + c];
    }
    for (int idx = tid; idx < 160; idx += blockDim.x) {
        int g = idx >> 4, c = idx & 15;
        int i = c_i1[g], s = c_s1[g];
        const float* B = (s == 0) ? ba : (s == 1) ? bb : (s == 2) ? bST11 : bST12;
        g_b1[idx] = B[i*16 + c];
    }
    for (int o = tid; o < 64; o += blockDim.x) {
        float sc = gamma[o] * rsqrtf(var[o] + 1e-5f);
        g_bd2[o] = (bd[o] + bd[64 + o] + bd[128 + o] - mean[o]) * sc + beta[o];
    }
}

// ---------------- kernel 0b: prepW ----------------
__global__ void prepW_kernel(const float* __restrict__ Wa, const float* __restrict__ Wb,
                             const float* __restrict__ WT1, const float* __restrict__ WT2,
                             const float* __restrict__ WST11, const float* __restrict__ WST12,
                             const float* __restrict__ Wd,
                             const float* __restrict__ gamma, const float* __restrict__ var) {
    const int gtid = blockIdx.x * blockDim.x + threadIdx.x;
    const int gsz = gridDim.x * blockDim.x;
    for (int idx = gtid; idx < 9 * 128 * 64; idx += gsz) {
        int tap = idx / 8192, r = idx % 8192;
        int m = r / 64, c = r % 64;
        int g = m >> 4;
        int i = c_i9[g], s = c_s9[g];
        const float* W = (s == 0) ? WT1 : (s == 1) ? WT2 : (s == 2) ? WST11 : WST12;
        g_W9b[idx] = __float2bfloat16(W[((i*16 + (m & 15))*64 + c)*9 + tap]);
    }
    for (int idx = gtid; idx < 160 * 64; idx += gsz) {
        int m = idx / 64, c = idx % 64;
        int g = m >> 4;
        int i = c_i1[g], s = c_s1[g];
        float val;
        if (s == 0)      val = Wa[(i*16 + (m & 15))*64 + c];
        else if (s == 1) val = Wb[(i*16 + (m & 15))*64 + c];
        else if (s == 2) val = WST11[((i*16 + (m & 15))*64 + c)*9 + 4];
        else             val = WST12[((i*16 + (m & 15))*64 + c)*9 + 4];
        g_W1b[idx] = __float2bfloat16(val);
    }
    // A-frag (R7-verified): j&1 -> row+8, j&2 -> col+4
    for (int idx = gtid; idx < 12288; idx += gsz) {
        int j = idx & 3, lane = (idx >> 2) & 31, kt = (idx >> 7) & 7, s = idx >> 10;
        int row = (lane >> 2) + ((j & 1) ? 8 : 0);
        int col = (lane & 3) + ((j & 2) ? 4 : 0);
        int m = 16 * s + row, c = 8 * kt + col;
        int i = m >> 6, o = m & 63;
        float sc = gamma[o] * rsqrtf(var[o] + 1e-5f);
        g_AfH[idx] = tf32r(Wd[(i * 64 + o) * 64 + c] * sc);
    }
}

// ---------------- kernel 1: unified conv + fused gram (ldmatrix B) ---------
#define XS_N_STRIDE 72
#define XS_ROWS     384
#define XS_BF16     (XS_ROWS * XS_N_STRIDE)     // 27648
#define FT_K        66
#define FT_BF16     (18 * 25 * FT_K)            // 29700
#define SMEM_CONV   ((XS_BF16 + FT_BF16) * 2)   // 114696 B

__global__ void __launch_bounds__(512, 2) convm_kernel(const float* __restrict__ x) {
    extern __shared__ __nv_bfloat16 smb[];
    __nv_bfloat16* xs = smb;
    __nv_bfloat16* fT = smb + XS_BF16;
    const int n = blockIdx.y, t0 = blockIdx.x * 4;
    const int tid = threadIdx.x, warp = tid >> 5, lane = tid & 31;

    {
        uint32_t* xz = (uint32_t*)xs;
        for (int i = tid; i < XS_BF16 / 2; i += 512) xz[i] = 0u;
    }
    __syncthreads();
    {
        const float* xn = x + (size_t)n * (CC * TT * VV);
        for (int idx = tid; idx < 64 * 12 * 25; idx += 512) {
            int cin = idx / 300, r = idx % 300;
            int tsl = r / 25, v = r % 25;
            int t = t0 - 4 + tsl;
            if (t < 0 || t >= TT) continue;
            xs[(tsl * 32 + v) * XS_N_STRIDE + cin] =
                __float2bfloat16(xn[(cin * TT + t) * VV + v]);
        }
    }
    __syncthreads();

    const int row = lane >> 2;
    const int kq  = (lane & 3) * 2;
    const int sel = lane >> 3, mrow = lane & 7;
    const uint32_t xs0 = smem_u32(xs);
    float acc[8][4];

    for (int ph = 0; ph < 3; ++ph) {
        if (ph == 2 && warp >= 4) break;
        int strip, half, is9;
        if (ph == 0) { strip = warp >> 1; half = warp & 1; is9 = 1; }
        else {
            int c1 = (ph == 1) ? warp : 16 + warp;
            strip = c1 >> 1; half = c1 & 1; is9 = 0;
        }
#pragma unroll
        for (int a = 0; a < 8; ++a)
#pragma unroll
            for (int b = 0; b < 4; ++b) acc[a][b] = 0.f;

        // per-lane ldmatrix base: rows = half*64 + ntp*16 + (sel>>1)*8 + mrow,
        // k-col = k0 + (sel&1)*8
        const uint32_t lmbase = xs0 + 2u * ((uint32_t)(half * 64 + (sel >> 1) * 8 + mrow)
                                            * XS_N_STRIDE + (sel & 1) * 8);
        const int ntaps = is9 ? 9 : 1;
        for (int jt = 0; jt < ntaps; ++jt) {
            const int tap = is9 ? jt : 4;
            const __nv_bfloat16* Ab = is9 ? g_W9b + (size_t)(tap * 128 + strip * 16) * 64
                                          : g_W1b + (size_t)strip * 16 * 64;
            const uint32_t tb_ = lmbase + 2u * (uint32_t)(tap * 32 * XS_N_STRIDE);
#pragma unroll
            for (int k0 = 0; k0 < 64; k0 += 16) {
                uint32_t a0 = *(const uint32_t*)(Ab + row * 64 + k0 + kq);
                uint32_t a1 = *(const uint32_t*)(Ab + (row + 8) * 64 + k0 + kq);
                uint32_t a2 = *(const uint32_t*)(Ab + row * 64 + k0 + kq + 8);
                uint32_t a3 = *(const uint32_t*)(Ab + (row + 8) * 64 + k0 + kq + 8);
#pragma unroll
                for (int ntp = 0; ntp < 4; ++ntp) {
                    uint32_t b0, b1, b2, b3;
                    ldsm4(b0, b1, b2, b3,
                          tb_ + 2u * (uint32_t)(ntp * 16 * XS_N_STRIDE + k0));
                    mma_bf16(acc[2 * ntp],     a0, a1, a2, a3, b0, b1);
                    mma_bf16(acc[2 * ntp + 1], a0, a1, a2, a3, b2, b3);
                }
            }
        }
        const int fstrip = is9 ? strip : 8 + strip;
        const float* bias_arr = is9 ? g_b9 + strip * 16 : g_b1 + strip * 16;
        const float bias_lo = bias_arr[row];
        const float bias_hi = bias_arr[row + 8];
#pragma unroll
        for (int nt = 0; nt < 8; ++nt)
#pragma unroll
            for (int j = 0; j < 4; ++j) {
                const int ch = row + ((j >= 2) ? 8 : 0);
                const int nl = half * 64 + nt * 8 + (lane & 3) * 2 + (j & 1);
                const int tt = nl >> 5, v = nl & 31;
                if (v < 25)
                    fT[(fstrip * 25 + v) * FT_K + ch * 4 + tt] =
                        __float2bfloat16(acc[nt][j] + ((j >= 2) ? bias_hi : bias_lo));
            }
    }
    __syncthreads();

    // gram: 450 workers = 9 pairs x 25 cells x 2 k-halves (k=32 each)
    if (tid < 450) {
        const int pair = tid / 50, rem = tid % 50;
        const int kh = rem / 25, cell = rem % 25;
        const int v0 = (cell / 5) * 5, w0 = (cell % 5) * 5;
        int br1, gi, gj;
        if (pair < 4) { br1 = 2 * pair;           gi = c_gi9[pair];      gj = c_gj9[pair]; }
        else          { br1 = 8 + 2 * (pair - 4); gi = c_gi1[pair - 4];  gj = c_gj1[pair - 4]; }
        const __nv_bfloat16* f1 = fT + (size_t)(br1 * 25 + v0) * FT_K + kh * 32;
        const __nv_bfloat16* f2 = fT + (size_t)((br1 + 1) * 25 + w0) * FT_K + kh * 32;
        ull g[5][5];
#pragma unroll
        for (int r = 0; r < 5; ++r)
#pragma unroll
            for (int s = 0; s < 5; ++s) g[r][s] = 0ULL;
        for (int kp = 0; kp < 16; ++kp) {
            ull a[5], b[5];
#pragma unroll
            for (int r = 0; r < 5; ++r) {
                float2 fa = __bfloat1622float2(*(const __nv_bfloat162*)(f1 + r * FT_K + kp * 2));
                a[r] = pack2(fa.x, fa.y);
            }
#pragma unroll
            for (int s = 0; s < 5; ++s) {
                float2 fb = __bfloat1622float2(*(const __nv_bfloat162*)(f2 + s * FT_K + kp * 2));
                b[s] = pack2(fb.x, fb.y);
            }
#pragma unroll
            for (int r = 0; r < 5; ++r)
#pragma unroll
                for (int s = 0; s < 5; ++s) fma2(g[r][s], a[r], b[s]);
        }
        float* dst = g_Gram + ((size_t)(n * 3 + gi) * 3 + gj) * 625;
#pragma unroll
        for (int r = 0; r < 5; ++r)
#pragma unroll
            for (int s = 0; s < 5; ++s) {
                float2 f = unpack2(g[r][s]);
                atomicAdd(&dst[(v0 + r) * 25 + (w0 + s)], f.x + f.y);
            }
    }
}

// ---------------- kernel 2: softmax + combine into A1 ----------------------
__global__ void smx_kernel(const float* __restrict__ weights) {
    const int n = blockIdx.x, i = blockIdx.y, w = threadIdx.x;
    if (w >= 25) return;
    const float INV = 1.f / 4096.f;
    const float wj[3] = {weights[5], weights[6], weights[7]};
    float a1[25];
#pragma unroll
    for (int v = 0; v < 25; ++v) a1[v] = g_Acomb[v * 25 + w];
    for (int j = 0; j < 3; ++j) {
        const float* gb = g_Gram + ((size_t)(n * 3 + i) * 3 + j) * 625 + w;
        float m = -1e30f;
        for (int v = 0; v < 25; ++v) m = fmaxf(m, gb[v * 25] * INV);
        float s = 0.f;
        for (int v = 0; v < 25; ++v) s += expf(gb[v * 25] * INV - m);
        float inv = wj[j] / s;
        for (int v = 0; v < 25; ++v) a1[v] += inv * expf(gb[v * 25] * INV - m);
    }
    float* out = g_A1 + (size_t)(n * 3 + i) * 625 + w;
    for (int v = 0; v < 25; ++v) out[v * 25] = a1[v];
}

// ---------------- kernel 3: fin2 (single-pass tf32 W) ----------------------
// grid (64 tb of 4t, 64 n), 512 thr, 2 blocks/SM.
#define F2_U    0
#define F2_XS   20160
#define F2_A1   26816
#define SMEM_F2 115072

__global__ void __launch_bounds__(512, 2) fin2_kernel(const float* __restrict__ x,
                                                      float* __restrict__ out) {
    extern __shared__ float sm[];
    float* U  = sm + F2_U;          // stride 105
    float* xs = sm + F2_XS;         // stride 104 (104%32=8 -> B-frag bijection)
    ull* A1u  = (ull*)(sm + F2_A1); // [i*25+v][13 wp]
    const int tb = blockIdx.x, nb = blockIdx.y, tid = threadIdx.x;
    const int warp = tid >> 5, lane = tid & 31;

    for (int idx = tid; idx < 64 * 104; idx += 512) {
        int c = idx / 104, j = idx % 104;
        xs[idx] = (j < 100)
            ? tf32r(x[((size_t)(nb * 64 + c)) * 6400 + tb * 100 + j]) : 0.f;
    }
    for (int idx = tid; idx < 975; idx += 512) {
        int wp = idx % 13, r = idx / 13;
        const float* a = g_A1 + (size_t)nb * 1875 + (r / 25) * 625 + (r % 25) * 25;
        float lo = a[2 * wp];
        float hi = (2 * wp + 1 < 25) ? a[2 * wp + 1] : 0.f;
        A1u[idx] = pack2(lo, hi);
    }
    __syncthreads();

    // G1: 24 sub-jobs = 12 strips x 2 n-halves (7 nt each, middle tile shared)
    const uint32_t* xsu = (const uint32_t*)xs;
    const float4* AH4 = (const float4*)g_AfH;
    for (int jj = 0; jj < 2; ++jj) {
        if (jj == 1 && warp >= 8) break;
        const int sj = jj ? 16 + warp : warp;
        if (sj >= 24) continue;
        const int strip = sj >> 1, nh = sj & 1;
        const int nt0 = nh * 6;
        float acc[7][4];
#pragma unroll
        for (int a = 0; a < 7; ++a)
#pragma unroll
            for (int b = 0; b < 4; ++b) acc[a][b] = 0.f;
#pragma unroll
        for (int kt = 0; kt < 8; ++kt) {
            float4 ah = AH4[(strip * 8 + kt) * 32 + lane];
            const uint32_t* xb0 = xsu + (8 * kt + (lane & 3)) * 104 + (lane >> 2);
            const uint32_t* xb1 = xb0 + 4 * 104;
#pragma unroll
            for (int nt = 0; nt < 7; ++nt) {
                uint32_t b0 = xb0[(nt0 + nt) * 8];
                uint32_t b1 = xb1[(nt0 + nt) * 8];
                mma_tf32(acc[nt], ah, b0, b1);
            }
        }
        // D-frag store: j&2 -> row+8, j&1 -> col+1 (R7-verified)
#pragma unroll
        for (int nt = 0; nt < 7; ++nt)
#pragma unroll
            for (int j = 0; j < 4; ++j) {
                int r = 16 * strip + (lane >> 2) + ((j & 2) ? 8 : 0);
                int col = (nt0 + nt) * 8 + 2 * (lane & 3) + (j & 1);
                U[r * 105 + col] = acc[nt][j];
            }
    }
    __syncthreads();

    // G2: thread = (t:4, o:64, wh:2)
    {
        const int t = tid >> 7, o = (tid >> 1) & 63, wh = tid & 1;
        const int wp0 = wh * 6;
        ull acc[7];
#pragma unroll
        for (int wp = 0; wp < 7; ++wp) acc[wp] = 0ULL;
#pragma unroll
        for (int i = 0; i < 3; ++i) {
            const float* Up = U + (i * 64 + o) * 105 + t * 25;
            const ull* Ap = A1u + i * 325;
#pragma unroll
            for (int v = 0; v < 25; ++v) {
                float u = Up[v];
                ull uu = pack2(u, u);
                const ull* a = Ap + v * 13 + wp0;
#pragma unroll
                for (int wp = 0; wp < 7; ++wp) fma2(acc[wp], uu, a[wp]);
            }
        }
        const float bias = g_bd2[o];
        const size_t base = ((size_t)(nb * 64 + o)) * 6400 + (size_t)(tb * 4 + t) * 25;
#pragma unroll
        for (int wp = 0; wp < 7; ++wp) {
            float2 f = unpack2(acc[wp]);
            int w = 2 * (wp0 + wp);
            out[base + w] = fmaxf(f.x + bias + x[base + w], 0.f);
            if (w + 1 < 25)
                out[base + w + 1] = fmaxf(f.y + bias + x[base + w + 1], 0.f);
        }
    }
}

// ---------------- launch ----------------------------------------------------
extern "C" void kernel_launch(void* const* d_in, const int* in_sizes, int n_in,
                              void* d_out, int out_size) {
    const float* x       = (const float*)d_in[0];
    const float* weights = (const float*)d_in[1];
    const float* A       = (const float*)d_in[2];
    const float* Wa      = (const float*)d_in[3];
    const float* ba      = (const float*)d_in[4];
    const float* Wb      = (const float*)d_in[5];
    const float* bb      = (const float*)d_in[6];
    const float* Wd      = (const float*)d_in[7];
    const float* bd      = (const float*)d_in[8];
    const float* WT1     = (const float*)d_in[9];
    const float* bT1     = (const float*)d_in[10];
    const float* WT2     = (const float*)d_in[11];
    const float* bT2     = (const float*)d_in[12];
    const float* WST11   = (const float*)d_in[13];
    const float* bST11   = (const float*)d_in[14];
    const float* WST12   = (const float*)d_in[15];
    const float* bST12   = (const float*)d_in[16];
    const float* bn_g    = (const float*)d_in[17];
    const float* bn_b    = (const float*)d_in[18];
    const float* bn_m    = (const float*)d_in[19];
    const float* bn_v    = (const float*)d_in[20];
    float* out = (float*)d_out;

    cudaFuncSetAttribute(convm_kernel, cudaFuncAttributeMaxDynamicSharedMemorySize, SMEM_CONV);
    cudaFuncSetAttribute(fin2_kernel,  cudaFuncAttributeMaxDynamicSharedMemorySize, SMEM_F2);

    void* gram_ptr = nullptr;
    cudaGetSymbolAddress(&gram_ptr, g_Gram);

    prepA_kernel<<<1, 640>>>(weights, A, ba, bb, bT1, bT2, bST11, bST12,
                             bd, bn_g, bn_b, bn_m, bn_v);
    prepW_kernel<<<64, 256>>>(Wa, Wb, WT1, WT2, WST11, WST12, Wd, bn_g, bn_v);
    cudaMemsetAsync(gram_ptr, 0, sizeof(float) * 64 * 9 * 625);
    convm_kernel<<<dim3(TT / 4, NB), 512, SMEM_CONV>>>(x);
    smx_kernel<<<dim3(NB, 3), 32>>>(weights);
    fin2_kernel<<<dim3(TT / 4, NB), 512, SMEM_F2>>>(x, out);
}

// round 13
// speedup vs baseline: 1.1875x; 1.1875x over previous
#include <cuda_runtime.h>
#include <cuda_bf16.h>
#include <cstdint>

#define NB   64
#define CC   64
#define TT   256
#define VV   25

typedef unsigned long long ull;

// ---------------- scratch (static device memory) ----------------
__device__ __align__(16) __nv_bfloat16 g_W9b[9 * 128 * 64];  // [tap][ch][cin]
__device__ __align__(16) __nv_bfloat16 g_W1b[160 * 64];      // [ch][cin]
__device__ float g_b9[128];
__device__ float g_b1[160];
__device__ float g_Acomb[625];
__device__ float g_Gram[64 * 9 * 625];
__device__ float g_A1[64 * 3 * 625];
// tf32 A-fragments of WdS^stacked [192 x 64]: [12 strip][8 kt][32 lane][4]
__device__ __align__(16) float g_AfH[12288];
__device__ float g_bd2[64];

// branch tables
__constant__ int c_i9[8]  = {0,0,1,1,1,1,2,2};
__constant__ int c_s9[8]  = {0,1,0,1,2,3,0,1};
__constant__ int c_i1[10] = {0,0,0,0,1,1,2,2,2,2};
__constant__ int c_s1[10] = {0,1,2,3,0,1,0,1,2,3};
__constant__ int c_gi9[4] = {0,1,1,2};
__constant__ int c_gj9[4] = {1,1,2,1};
__constant__ int c_gi1[5] = {0,0,1,2,2};
__constant__ int c_gj1[5] = {0,2,0,0,2};

// ---------------- helpers ----------------
__device__ __forceinline__ ull pack2(float lo, float hi) {
    ull r; asm("mov.b64 %0, {%1,%2};" : "=l"(r) : "f"(lo), "f"(hi)); return r;
}
__device__ __forceinline__ void fma2(ull& d, ull a, ull b) {
    asm("fma.rn.f32x2 %0, %1, %2, %0;" : "+l"(d) : "l"(a), "l"(b));
}
__device__ __forceinline__ float2 unpack2(ull p) {
    float2 f; asm("mov.b64 {%0,%1}, %2;" : "=f"(f.x), "=f"(f.y) : "l"(p)); return f;
}
__device__ __forceinline__ float tf32r(float f) {
    uint32_t u;
    asm("cvt.rn.tf32.f32 %0, %1;" : "=r"(u) : "f"(f));
    return __uint_as_float(u);
}
__device__ __forceinline__ void mma_bf16(float* d, uint32_t a0, uint32_t a1,
                                         uint32_t a2, uint32_t a3,
                                         uint32_t b0, uint32_t b1) {
    asm volatile(
        "mma.sync.aligned.m16n8k16.row.col.f32.bf16.bf16.f32 "
        "{%0,%1,%2,%3}, {%4,%5,%6,%7}, {%8,%9}, {%0,%1,%2,%3};"
        : "+f"(d[0]), "+f"(d[1]), "+f"(d[2]), "+f"(d[3])
        : "r"(a0), "r"(a1), "r"(a2), "r"(a3), "r"(b0), "r"(b1));
}
__device__ __forceinline__ void mma_tf32(float* d, float4 a, uint32_t b0, uint32_t b1) {
    asm volatile(
        "mma.sync.aligned.m16n8k8.row.col.f32.tf32.tf32.f32 "
        "{%0,%1,%2,%3}, {%4,%5,%6,%7}, {%8,%9}, {%0,%1,%2,%3};"
        : "+f"(d[0]), "+f"(d[1]), "+f"(d[2]), "+f"(d[3])
        : "r"(__float_as_uint(a.x)), "r"(__float_as_uint(a.y)),
          "r"(__float_as_uint(a.z)), "r"(__float_as_uint(a.w)),
          "r"(b0), "r"(b1));
}

// ---------------- kernel 0a: prepA ----------------
__global__ void prepA_kernel(const float* __restrict__ weights, const float* __restrict__ A,
                             const float* __restrict__ ba, const float* __restrict__ bb,
                             const float* __restrict__ bT1, const float* __restrict__ bT2,
                             const float* __restrict__ bST11, const float* __restrict__ bST12,
                             const float* __restrict__ bd,
                             const float* __restrict__ gamma, const float* __restrict__ beta,
                             const float* __restrict__ mean, const float* __restrict__ var) {
    __shared__ float sA[625], sA4[625];
    const int tid = threadIdx.x;
    if (tid < 625) {
        float a = A[tid];
        sA[tid] = a;
        int v = tid / 25, w = tid % 25;
        float a2 = a * a;  // elementwise Chebyshev (torch.pow semantics)
        sA4[tid] = 8.f * a2 * a2 - 8.f * a2 + (v == w ? 1.f : 0.f);
    }
    __syncthreads();
    if (tid < 25) {
        const int w = tid;
        float w0 = weights[0], w1 = weights[1];
        float m = -1e30f;
        for (int v = 0; v < 25; ++v) m = fmaxf(m, sA4[v*25+w] * 0.04f);
        float ssum = 0.f;
        for (int v = 0; v < 25; ++v) ssum += expf(sA4[v*25+w] * 0.04f - m);
        float inv = 1.f / ssum;
        for (int v = 0; v < 25; ++v)
            g_Acomb[v*25+w] = w0 * sA[v*25+w] + w1 * expf(sA4[v*25+w] * 0.04f - m) * inv;
    }
    for (int idx = tid; idx < 128; idx += blockDim.x) {
        int g = idx >> 4, c = idx & 15;
        int i = c_i9[g], s = c_s9[g];
        const float* B = (s == 0) ? bT1 : (s == 1) ? bT2 : (s == 2) ? bST11 : bST12;
        g_b9[idx] = B[i*16 + c];
    }
    for (int idx = tid; idx < 160; idx += blockDim.x) {
        int g = idx >> 4, c = idx & 15;
        int i = c_i1[g], s = c_s1[g];
        const float* B = (s == 0) ? ba : (s == 1) ? bb : (s == 2) ? bST11 : bST12;
        g_b1[idx] = B[i*16 + c];
    }
    for (int o = tid; o < 64; o += blockDim.x) {
        float sc = gamma[o] * rsqrtf(var[o] + 1e-5f);
        g_bd2[o] = (bd[o] + bd[64 + o] + bd[128 + o] - mean[o]) * sc + beta[o];
    }
}

// ---------------- kernel 0b: prepW ----------------
__global__ void prepW_kernel(const float* __restrict__ Wa, const float* __restrict__ Wb,
                             const float* __restrict__ WT1, const float* __restrict__ WT2,
                             const float* __restrict__ WST11, const float* __restrict__ WST12,
                             const float* __restrict__ Wd,
                             const float* __restrict__ gamma, const float* __restrict__ var) {
    const int gtid = blockIdx.x * blockDim.x + threadIdx.x;
    const int gsz = gridDim.x * blockDim.x;
    for (int idx = gtid; idx < 9 * 128 * 64; idx += gsz) {
        int tap = idx / 8192, r = idx % 8192;
        int m = r / 64, c = r % 64;
        int g = m >> 4;
        int i = c_i9[g], s = c_s9[g];
        const float* W = (s == 0) ? WT1 : (s == 1) ? WT2 : (s == 2) ? WST11 : WST12;
        g_W9b[idx] = __float2bfloat16(W[((i*16 + (m & 15))*64 + c)*9 + tap]);
    }
    for (int idx = gtid; idx < 160 * 64; idx += gsz) {
        int m = idx / 64, c = idx % 64;
        int g = m >> 4;
        int i = c_i1[g], s = c_s1[g];
        float val;
        if (s == 0)      val = Wa[(i*16 + (m & 15))*64 + c];
        else if (s == 1) val = Wb[(i*16 + (m & 15))*64 + c];
        else if (s == 2) val = WST11[((i*16 + (m & 15))*64 + c)*9 + 4];
        else             val = WST12[((i*16 + (m & 15))*64 + c)*9 + 4];
        g_W1b[idx] = __float2bfloat16(val);
    }
    // A-frag (R7-verified): j&1 -> row+8, j&2 -> col+4
    for (int idx = gtid; idx < 12288; idx += gsz) {
        int j = idx & 3, lane = (idx >> 2) & 31, kt = (idx >> 7) & 7, s = idx >> 10;
        int row = (lane >> 2) + ((j & 1) ? 8 : 0);
        int col = (lane & 3) + ((j & 2) ? 4 : 0);
        int m = 16 * s + row, c = 8 * kt + col;
        int i = m >> 6, o = m & 63;
        float sc = gamma[o] * rsqrtf(var[o] + 1e-5f);
        g_AfH[idx] = tf32r(Wd[(i * 64 + o) * 64 + c] * sc);
    }
}

// ---------------- kernel 1: unified conv + fused gram (R10 plain-LDS) ------
#define XS_N_STRIDE 72
#define XS_ROWS     384
#define XS_BF16     (XS_ROWS * XS_N_STRIDE)     // 27648
#define FT_K        66
#define FT_BF16     (18 * 25 * FT_K)            // 29700
#define SMEM_CONV   ((XS_BF16 + FT_BF16) * 2)   // 114696 B

__global__ void __launch_bounds__(512, 2) convm_kernel(const float* __restrict__ x) {
    extern __shared__ __nv_bfloat16 smb[];
    __nv_bfloat16* xs = smb;
    __nv_bfloat16* fT = smb + XS_BF16;
    const int n = blockIdx.y, t0 = blockIdx.x * 4;
    const int tid = threadIdx.x, warp = tid >> 5, lane = tid & 31;

    {
        uint32_t* xz = (uint32_t*)xs;
        for (int i = tid; i < XS_BF16 / 2; i += 512) xz[i] = 0u;
    }
    __syncthreads();
    {
        const float* xn = x + (size_t)n * (CC * TT * VV);
        for (int idx = tid; idx < 64 * 12 * 25; idx += 512) {
            int cin = idx / 300, r = idx % 300;
            int tsl = r / 25, v = r % 25;
            int t = t0 - 4 + tsl;
            if (t < 0 || t >= TT) continue;
            xs[(tsl * 32 + v) * XS_N_STRIDE + cin] =
                __float2bfloat16(xn[(cin * TT + t) * VV + v]);
        }
    }
    __syncthreads();

    const int row = lane >> 2;
    const int kq  = (lane & 3) * 2;
    float acc[8][4];

    for (int ph = 0; ph < 3; ++ph) {
        if (ph == 2 && warp >= 4) break;
        int strip, half, is9;
        if (ph == 0) { strip = warp >> 1; half = warp & 1; is9 = 1; }
        else {
            int c1 = (ph == 1) ? warp : 16 + warp;
            strip = c1 >> 1; half = c1 & 1; is9 = 0;
        }
#pragma unroll
        for (int a = 0; a < 8; ++a)
#pragma unroll
            for (int b = 0; b < 4; ++b) acc[a][b] = 0.f;

        const int ntaps = is9 ? 9 : 1;
        for (int jt = 0; jt < ntaps; ++jt) {
            const int tap = is9 ? jt : 4;
            const __nv_bfloat16* Ab = is9 ? g_W9b + (size_t)(tap * 128 + strip * 16) * 64
                                          : g_W1b + (size_t)strip * 16 * 64;
            const __nv_bfloat16* xb = xs + (size_t)(tap * 32 + half * 64 + row) * XS_N_STRIDE;
#pragma unroll
            for (int k0 = 0; k0 < 64; k0 += 16) {
                uint32_t a0 = *(const uint32_t*)(Ab + row * 64 + k0 + kq);
                uint32_t a1 = *(const uint32_t*)(Ab + (row + 8) * 64 + k0 + kq);
                uint32_t a2 = *(const uint32_t*)(Ab + row * 64 + k0 + kq + 8);
                uint32_t a3 = *(const uint32_t*)(Ab + (row + 8) * 64 + k0 + kq + 8);
#pragma unroll
                for (int nt = 0; nt < 8; ++nt) {
                    uint32_t b0 = *(const uint32_t*)(xb + nt * 8 * XS_N_STRIDE + k0 + kq);
                    uint32_t b1 = *(const uint32_t*)(xb + nt * 8 * XS_N_STRIDE + k0 + kq + 8);
                    mma_bf16(acc[nt], a0, a1, a2, a3, b0, b1);
                }
            }
        }
        const int fstrip = is9 ? strip : 8 + strip;
        const float* bias_arr = is9 ? g_b9 + strip * 16 : g_b1 + strip * 16;
        const float bias_lo = bias_arr[row];
        const float bias_hi = bias_arr[row + 8];
#pragma unroll
        for (int nt = 0; nt < 8; ++nt)
#pragma unroll
            for (int j = 0; j < 4; ++j) {
                const int ch = row + ((j >= 2) ? 8 : 0);
                const int nl = half * 64 + nt * 8 + (lane & 3) * 2 + (j & 1);
                const int tt = nl >> 5, v = nl & 31;
                if (v < 25)
                    fT[(fstrip * 25 + v) * FT_K + ch * 4 + tt] =
                        __float2bfloat16(acc[nt][j] + ((j >= 2) ? bias_hi : bias_lo));
            }
    }
    __syncthreads();

    // gram: 450 workers = 9 pairs x 25 cells x 2 k-halves (k=32 each)
    if (tid < 450) {
        const int pair = tid / 50, rem = tid % 50;
        const int kh = rem / 25, cell = rem % 25;
        const int v0 = (cell / 5) * 5, w0 = (cell % 5) * 5;
        int br1, gi, gj;
        if (pair < 4) { br1 = 2 * pair;           gi = c_gi9[pair];      gj = c_gj9[pair]; }
        else          { br1 = 8 + 2 * (pair - 4); gi = c_gi1[pair - 4];  gj = c_gj1[pair - 4]; }
        const __nv_bfloat16* f1 = fT + (size_t)(br1 * 25 + v0) * FT_K + kh * 32;
        const __nv_bfloat16* f2 = fT + (size_t)((br1 + 1) * 25 + w0) * FT_K + kh * 32;
        ull g[5][5];
#pragma unroll
        for (int r = 0; r < 5; ++r)
#pragma unroll
            for (int s = 0; s < 5; ++s) g[r][s] = 0ULL;
        for (int kp = 0; kp < 16; ++kp) {
            ull a[5], b[5];
#pragma unroll
            for (int r = 0; r < 5; ++r) {
                float2 fa = __bfloat1622float2(*(const __nv_bfloat162*)(f1 + r * FT_K + kp * 2));
                a[r] = pack2(fa.x, fa.y);
            }
#pragma unroll
            for (int s = 0; s < 5; ++s) {
                float2 fb = __bfloat1622float2(*(const __nv_bfloat162*)(f2 + s * FT_K + kp * 2));
                b[s] = pack2(fb.x, fb.y);
            }
#pragma unroll
            for (int r = 0; r < 5; ++r)
#pragma unroll
                for (int s = 0; s < 5; ++s) fma2(g[r][s], a[r], b[s]);
        }
        float* dst = g_Gram + ((size_t)(n * 3 + gi) * 3 + gj) * 625;
#pragma unroll
        for (int r = 0; r < 5; ++r)
#pragma unroll
            for (int s = 0; s < 5; ++s) {
                float2 f = unpack2(g[r][s]);
                atomicAdd(&dst[(v0 + r) * 25 + (w0 + s)], f.x + f.y);
            }
    }
}

// ---------------- kernel 2: softmax + combine into A1 ----------------------
__global__ void smx_kernel(const float* __restrict__ weights) {
    const int n = blockIdx.x, i = blockIdx.y, w = threadIdx.x;
    if (w >= 25) return;
    const float INV = 1.f / 4096.f;
    const float wj[3] = {weights[5], weights[6], weights[7]};
    float a1[25];
#pragma unroll
    for (int v = 0; v < 25; ++v) a1[v] = g_Acomb[v * 25 + w];
    for (int j = 0; j < 3; ++j) {
        const float* gb = g_Gram + ((size_t)(n * 3 + i) * 3 + j) * 625 + w;
        float m = -1e30f;
        for (int v = 0; v < 25; ++v) m = fmaxf(m, gb[v * 25] * INV);
        float s = 0.f;
        for (int v = 0; v < 25; ++v) s += expf(gb[v * 25] * INV - m);
        float inv = wj[j] / s;
        for (int v = 0; v < 25; ++v) a1[v] += inv * expf(gb[v * 25] * INV - m);
    }
    float* out = g_A1 + (size_t)(n * 3 + i) * 625 + w;
    for (int v = 0; v < 25; ++v) out[v * 25] = a1[v];
}

// ---------------- kernel 3: fin2 (single-pass tf32 W — the ONE new var) ----
// grid (64 tb of 4t, 64 n), 512 thr, 2 blocks/SM.
#define F2_U    0
#define F2_XS   20160
#define F2_A1   26816
#define SMEM_F2 115072

__global__ void __launch_bounds__(512, 2) fin2_kernel(const float* __restrict__ x,
                                                      float* __restrict__ out) {
    extern __shared__ float sm[];
    float* U  = sm + F2_U;          // stride 105
    float* xs = sm + F2_XS;         // stride 104 (104%32=8 -> B-frag bijection)
    ull* A1u  = (ull*)(sm + F2_A1); // [i*25+v][13 wp]
    const int tb = blockIdx.x, nb = blockIdx.y, tid = threadIdx.x;
    const int warp = tid >> 5, lane = tid & 31;

    for (int idx = tid; idx < 64 * 104; idx += 512) {
        int c = idx / 104, j = idx % 104;
        xs[idx] = (j < 100)
            ? tf32r(x[((size_t)(nb * 64 + c)) * 6400 + tb * 100 + j]) : 0.f;
    }
    for (int idx = tid; idx < 975; idx += 512) {
        int wp = idx % 13, r = idx / 13;
        const float* a = g_A1 + (size_t)nb * 1875 + (r / 25) * 625 + (r % 25) * 25;
        float lo = a[2 * wp];
        float hi = (2 * wp + 1 < 25) ? a[2 * wp + 1] : 0.f;
        A1u[idx] = pack2(lo, hi);
    }
    __syncthreads();

    // G1: 24 sub-jobs = 12 strips x 2 n-halves (7 nt each, middle tile shared)
    const uint32_t* xsu = (const uint32_t*)xs;
    const float4* AH4 = (const float4*)g_AfH;
    for (int jj = 0; jj < 2; ++jj) {
        if (jj == 1 && warp >= 8) break;
        const int sj = jj ? 16 + warp : warp;
        if (sj >= 24) continue;
        const int strip = sj >> 1, nh = sj & 1;
        const int nt0 = nh * 6;
        float acc[7][4];
#pragma unroll
        for (int a = 0; a < 7; ++a)
#pragma unroll
            for (int b = 0; b < 4; ++b) acc[a][b] = 0.f;
#pragma unroll
        for (int kt = 0; kt < 8; ++kt) {
            float4 ah = AH4[(strip * 8 + kt) * 32 + lane];
            const uint32_t* xb0 = xsu + (8 * kt + (lane & 3)) * 104 + (lane >> 2);
            const uint32_t* xb1 = xb0 + 4 * 104;
#pragma unroll
            for (int nt = 0; nt < 7; ++nt) {
                uint32_t b0 = xb0[(nt0 + nt) * 8];
                uint32_t b1 = xb1[(nt0 + nt) * 8];
                mma_tf32(acc[nt], ah, b0, b1);
            }
        }
        // D-frag store: j&2 -> row+8, j&1 -> col+1 (R7-verified)
#pragma unroll
        for (int nt = 0; nt < 7; ++nt)
#pragma unroll
            for (int j = 0; j < 4; ++j) {
                int r = 16 * strip + (lane >> 2) + ((j & 2) ? 8 : 0);
                int col = (nt0 + nt) * 8 + 2 * (lane & 3) + (j & 1);
                U[r * 105 + col] = acc[nt][j];
            }
    }
    __syncthreads();

    // G2: thread = (t:4, o:64, wh:2)
    {
        const int t = tid >> 7, o = (tid >> 1) & 63, wh = tid & 1;
        const int wp0 = wh * 6;
        ull acc[7];
#pragma unroll
        for (int wp = 0; wp < 7; ++wp) acc[wp] = 0ULL;
#pragma unroll
        for (int i = 0; i < 3; ++i) {
            const float* Up = U + (i * 64 + o) * 105 + t * 25;
            const ull* Ap = A1u + i * 325;
#pragma unroll
            for (int v = 0; v < 25; ++v) {
                float u = Up[v];
                ull uu = pack2(u, u);
                const ull* a = Ap + v * 13 + wp0;
#pragma unroll
                for (int wp = 0; wp < 7; ++wp) fma2(acc[wp], uu, a[wp]);
            }
        }
        const float bias = g_bd2[o];
        const size_t base = ((size_t)(nb * 64 + o)) * 6400 + (size_t)(tb * 4 + t) * 25;
#pragma unroll
        for (int wp = 0; wp < 7; ++wp) {
            float2 f = unpack2(acc[wp]);
            int w = 2 * (wp0 + wp);
            out[base + w] = fmaxf(f.x + bias + x[base + w], 0.f);
            if (w + 1 < 25)
                out[base + w + 1] = fmaxf(f.y + bias + x[base + w + 1], 0.f);
        }
    }
}

// ---------------- launch ----------------------------------------------------
extern "C" void kernel_launch(void* const* d_in, const int* in_sizes, int n_in,
                              void* d_out, int out_size) {
    const float* x       = (const float*)d_in[0];
    const float* weights = (const float*)d_in[1];
    const float* A       = (const float*)d_in[2];
    const float* Wa      = (const float*)d_in[3];
    const float* ba      = (const float*)d_in[4];
    const float* Wb      = (const float*)d_in[5];
    const float* bb      = (const float*)d_in[6];
    const float* Wd      = (const float*)d_in[7];
    const float* bd      = (const float*)d_in[8];
    const float* WT1     = (const float*)d_in[9];
    const float* bT1     = (const float*)d_in[10];
    const float* WT2     = (const float*)d_in[11];
    const float* bT2     = (const float*)d_in[12];
    const float* WST11   = (const float*)d_in[13];
    const float* bST11   = (const float*)d_in[14];
    const float* WST12   = (const float*)d_in[15];
    const float* bST12   = (const float*)d_in[16];
    const float* bn_g    = (const float*)d_in[17];
    const float* bn_b    = (const float*)d_in[18];
    const float* bn_m    = (const float*)d_in[19];
    const float* bn_v    = (const float*)d_in[20];
    float* out = (float*)d_out;

    cudaFuncSetAttribute(convm_kernel, cudaFuncAttributeMaxDynamicSharedMemorySize, SMEM_CONV);
    cudaFuncSetAttribute(fin2_kernel,  cudaFuncAttributeMaxDynamicSharedMemorySize, SMEM_F2);

    void* gram_ptr = nullptr;
    cudaGetSymbolAddress(&gram_ptr, g_Gram);

    prepA_kernel<<<1, 640>>>(weights, A, ba, bb, bT1, bT2, bST11, bST12,
                             bd, bn_g, bn_b, bn_m, bn_v);
    prepW_kernel<<<64, 256>>>(Wa, Wb, WT1, WT2, WST11, WST12, Wd, bn_g, bn_v);
    cudaMemsetAsync(gram_ptr, 0, sizeof(float) * 64 * 9 * 625);
    convm_kernel<<<dim3(TT / 4, NB), 512, SMEM_CONV>>>(x);
    smx_kernel<<<dim3(NB, 3), 32>>>(weights);
    fin2_kernel<<<dim3(TT / 4, NB), 512, SMEM_F2>>>(x, out);
}

// round 14
// speedup vs baseline: 1.4954x; 1.2593x over previous
#include <cuda_runtime.h>
#include <cuda_bf16.h>
#include <cstdint>

#define NB   64
#define CC   64
#define TT   256
#define VV   25

typedef unsigned long long ull;

// ---------------- scratch (static device memory) ----------------
__device__ __align__(16) uint8_t g_W9q[9 * 128 * 64];  // [tap][ch][cin] e4m3, x16
__device__ __align__(16) uint8_t g_W1q[160 * 64];      // [ch][cin] e4m3, x16
__device__ float g_b9[128];                            // x16
__device__ float g_b1[160];                            // x16
__device__ float g_Acomb[625];
__device__ float g_Gram[64 * 9 * 625];                 // x256
__device__ float g_A1[64 * 3 * 625];
// tf32 A-fragments of WdS^stacked [192 x 64]: [12 strip][8 kt][32 lane][4]
__device__ __align__(16) float g_AfH[12288];
__device__ float g_bd2[64];

// branch tables
__constant__ int c_i9[8]  = {0,0,1,1,1,1,2,2};
__constant__ int c_s9[8]  = {0,1,0,1,2,3,0,1};
__constant__ int c_i1[10] = {0,0,0,0,1,1,2,2,2,2};
__constant__ int c_s1[10] = {0,1,2,3,0,1,0,1,2,3};
__constant__ int c_gi9[4] = {0,1,1,2};
__constant__ int c_gj9[4] = {1,1,2,1};
__constant__ int c_gi1[5] = {0,0,1,2,2};
__constant__ int c_gj1[5] = {0,2,0,0,2};

// ---------------- helpers ----------------
__device__ __forceinline__ ull pack2(float lo, float hi) {
    ull r; asm("mov.b64 %0, {%1,%2};" : "=l"(r) : "f"(lo), "f"(hi)); return r;
}
__device__ __forceinline__ void fma2(ull& d, ull a, ull b) {
    asm("fma.rn.f32x2 %0, %1, %2, %0;" : "+l"(d) : "l"(a), "l"(b));
}
__device__ __forceinline__ float2 unpack2(ull p) {
    float2 f; asm("mov.b64 {%0,%1}, %2;" : "=f"(f.x), "=f"(f.y) : "l"(p)); return f;
}
__device__ __forceinline__ float tf32r(float f) {
    uint32_t u;
    asm("cvt.rn.tf32.f32 %0, %1;" : "=r"(u) : "f"(f));
    return __uint_as_float(u);
}
// pack (hi, lo) floats into two e4m3 bytes (first operand -> high byte)
__device__ __forceinline__ uint16_t f2e4m3x2(float hi, float lo) {
    uint16_t u;
    asm("cvt.rn.satfinite.e4m3x2.f32 %0, %1, %2;" : "=h"(u) : "f"(hi), "f"(lo));
    return u;
}
__device__ __forceinline__ void mma_e4m3(float* d, uint32_t a0, uint32_t a1,
                                         uint32_t a2, uint32_t a3,
                                         uint32_t b0, uint32_t b1) {
    asm volatile(
        "mma.sync.aligned.m16n8k32.row.col.f32.e4m3.e4m3.f32 "
        "{%0,%1,%2,%3}, {%4,%5,%6,%7}, {%8,%9}, {%0,%1,%2,%3};"
        : "+f"(d[0]), "+f"(d[1]), "+f"(d[2]), "+f"(d[3])
        : "r"(a0), "r"(a1), "r"(a2), "r"(a3), "r"(b0), "r"(b1));
}
__device__ __forceinline__ void mma_tf32(float* d, float4 a, uint32_t b0, uint32_t b1) {
    asm volatile(
        "mma.sync.aligned.m16n8k8.row.col.f32.tf32.tf32.f32 "
        "{%0,%1,%2,%3}, {%4,%5,%6,%7}, {%8,%9}, {%0,%1,%2,%3};"
        : "+f"(d[0]), "+f"(d[1]), "+f"(d[2]), "+f"(d[3])
        : "r"(__float_as_uint(a.x)), "r"(__float_as_uint(a.y)),
          "r"(__float_as_uint(a.z)), "r"(__float_as_uint(a.w)),
          "r"(b0), "r"(b1));
}

// ---------------- kernel 0a: prepA ----------------
__global__ void prepA_kernel(const float* __restrict__ weights, const float* __restrict__ A,
                             const float* __restrict__ ba, const float* __restrict__ bb,
                             const float* __restrict__ bT1, const float* __restrict__ bT2,
                             const float* __restrict__ bST11, const float* __restrict__ bST12,
                             const float* __restrict__ bd,
                             const float* __restrict__ gamma, const float* __restrict__ beta,
                             const float* __restrict__ mean, const float* __restrict__ var) {
    __shared__ float sA[625], sA4[625];
    const int tid = threadIdx.x;
    if (tid < 625) {
        float a = A[tid];
        sA[tid] = a;
        int v = tid / 25, w = tid % 25;
        float a2 = a * a;  // elementwise Chebyshev (torch.pow semantics)
        sA4[tid] = 8.f * a2 * a2 - 8.f * a2 + (v == w ? 1.f : 0.f);
    }
    __syncthreads();
    if (tid < 25) {
        const int w = tid;
        float w0 = weights[0], w1 = weights[1];
        float m = -1e30f;
        for (int v = 0; v < 25; ++v) m = fmaxf(m, sA4[v*25+w] * 0.04f);
        float ssum = 0.f;
        for (int v = 0; v < 25; ++v) ssum += expf(sA4[v*25+w] * 0.04f - m);
        float inv = 1.f / ssum;
        for (int v = 0; v < 25; ++v)
            g_Acomb[v*25+w] = w0 * sA[v*25+w] + w1 * expf(sA4[v*25+w] * 0.04f - m) * inv;
    }
    // biases x16 (fp8 weight scale)
    for (int idx = tid; idx < 128; idx += blockDim.x) {
        int g = idx >> 4, c = idx & 15;
        int i = c_i9[g], s = c_s9[g];
        const float* B = (s == 0) ? bT1 : (s == 1) ? bT2 : (s == 2) ? bST11 : bST12;
        g_b9[idx] = 16.f * B[i*16 + c];
    }
    for (int idx = tid; idx < 160; idx += blockDim.x) {
        int g = idx >> 4, c = idx & 15;
        int i = c_i1[g], s = c_s1[g];
        const float* B = (s == 0) ? ba : (s == 1) ? bb : (s == 2) ? bST11 : bST12;
        g_b1[idx] = 16.f * B[i*16 + c];
    }
    for (int o = tid; o < 64; o += blockDim.x) {
        float sc = gamma[o] * rsqrtf(var[o] + 1e-5f);
        g_bd2[o] = (bd[o] + bd[64 + o] + bd[128 + o] - mean[o]) * sc + beta[o];
    }
}

// ---------------- kernel 0b: prepW ----------------
__global__ void prepW_kernel(const float* __restrict__ Wa, const float* __restrict__ Wb,
                             const float* __restrict__ WT1, const float* __restrict__ WT2,
                             const float* __restrict__ WST11, const float* __restrict__ WST12,
                             const float* __restrict__ Wd,
                             const float* __restrict__ gamma, const float* __restrict__ var) {
    const int gtid = blockIdx.x * blockDim.x + threadIdx.x;
    const int gsz = gridDim.x * blockDim.x;
    // 9-tap weights -> e4m3 x16, u16 pair writes
    for (int idx = gtid; idx < 9 * 128 * 32; idx += gsz) {
        int tap = idx / 4096, r = idx % 4096;
        int m = r / 32, cp = r % 32;
        int g = m >> 4;
        int i = c_i9[g], s = c_s9[g];
        const float* W = (s == 0) ? WT1 : (s == 1) ? WT2 : (s == 2) ? WST11 : WST12;
        const float* base = W + ((size_t)(i*16 + (m & 15))*64) * 9 + tap;
        float w0 = 16.f * base[(2*cp) * 9];
        float w1 = 16.f * base[(2*cp + 1) * 9];
        ((uint16_t*)g_W9q)[idx] = f2e4m3x2(w1, w0);
    }
    for (int idx = gtid; idx < 160 * 32; idx += gsz) {
        int m = idx / 32, cp = idx % 32;
        int g = m >> 4;
        int i = c_i1[g], s = c_s1[g];
        float w0, w1;
        if (s == 0)      { w0 = Wa[(i*16+(m&15))*64 + 2*cp];      w1 = Wa[(i*16+(m&15))*64 + 2*cp+1]; }
        else if (s == 1) { w0 = Wb[(i*16+(m&15))*64 + 2*cp];      w1 = Wb[(i*16+(m&15))*64 + 2*cp+1]; }
        else if (s == 2) { w0 = WST11[((i*16+(m&15))*64 + 2*cp)*9 + 4];
                           w1 = WST11[((i*16+(m&15))*64 + 2*cp+1)*9 + 4]; }
        else             { w0 = WST12[((i*16+(m&15))*64 + 2*cp)*9 + 4];
                           w1 = WST12[((i*16+(m&15))*64 + 2*cp+1)*9 + 4]; }
        ((uint16_t*)g_W1q)[idx] = f2e4m3x2(16.f * w1, 16.f * w0);
    }
    // A-frag (R7-verified): j&1 -> row+8, j&2 -> col+4
    for (int idx = gtid; idx < 12288; idx += gsz) {
        int j = idx & 3, lane = (idx >> 2) & 31, kt = (idx >> 7) & 7, s = idx >> 10;
        int row = (lane >> 2) + ((j & 1) ? 8 : 0);
        int col = (lane & 3) + ((j & 2) ? 4 : 0);
        int m = 16 * s + row, c = 8 * kt + col;
        int i = m >> 6, o = m & 63;
        float sc = gamma[o] * rsqrtf(var[o] + 1e-5f);
        g_AfH[idx] = tf32r(Wd[(i * 64 + o) * 64 + c] * sc);
    }
}

// ---------------- kernel 1: unified conv (fp8 mma) + fused gram ------------
// xs: fp8 [384 rows (12 tsl x 32 v)][144B rows, 64 valid cin]
//     36-word rows: (4r+q) bank bijection for u32 B-frag loads.
// fT: [18 br][25 v][66 kpad] bf16 (values x16), k = (ch%16)*4 + tt
#define XS_ROW_B    144
#define XS_BYTES    (384 * XS_ROW_B)            // 55296
#define FT_K        66
#define FT_BF16     (18 * 25 * FT_K)            // 29700
#define SMEM_CONV   (XS_BYTES + FT_BF16 * 2)    // 114696 B

__global__ void __launch_bounds__(512, 2) convm_kernel(const float* __restrict__ x) {
    extern __shared__ uint8_t smu[];
    uint8_t* xs = smu;
    __nv_bfloat16* fT = (__nv_bfloat16*)(smu + XS_BYTES);
    const int n = blockIdx.y, t0 = blockIdx.x * 4;
    const int tid = threadIdx.x, warp = tid >> 5, lane = tid & 31;

    // stage x -> e4m3 (inline OOB zeros; pad v-rows/cin-bytes left uninit, never read)
    {
        const float* xn = x + (size_t)n * (CC * TT * VV);
        for (int idx = tid; idx < 64 * 12 * 25; idx += 512) {
            int cin = idx / 300, r = idx % 300;
            int tsl = r / 25, v = r % 25;
            int t = t0 - 4 + tsl;
            float val = (t >= 0 && t < TT) ? xn[(cin * TT + t) * VV + v] : 0.f;
            xs[(tsl * 32 + v) * XS_ROW_B + cin] = (uint8_t)f2e4m3x2(0.f, val);
        }
    }
    __syncthreads();

    const int row = lane >> 2;
    const int kq4 = (lane & 3) * 4;
    float acc[8][4];

    for (int ph = 0; ph < 3; ++ph) {
        if (ph == 2 && warp >= 4) break;
        int strip, half, is9;
        if (ph == 0) { strip = warp >> 1; half = warp & 1; is9 = 1; }
        else {
            int c1 = (ph == 1) ? warp : 16 + warp;
            strip = c1 >> 1; half = c1 & 1; is9 = 0;
        }
#pragma unroll
        for (int a = 0; a < 8; ++a)
#pragma unroll
            for (int b = 0; b < 4; ++b) acc[a][b] = 0.f;

        const int ntaps = is9 ? 9 : 1;
        for (int jt = 0; jt < ntaps; ++jt) {
            const int tap = is9 ? jt : 4;
            const uint8_t* Ab = is9 ? g_W9q + (size_t)(tap * 128 + strip * 16) * 64
                                    : g_W1q + (size_t)strip * 16 * 64;
            const uint8_t* xb = xs + (size_t)(tap * 32 + half * 64 + row) * XS_ROW_B;
#pragma unroll
            for (int k0 = 0; k0 < 64; k0 += 32) {
                uint32_t a0 = *(const uint32_t*)(Ab + row * 64 + k0 + kq4);
                uint32_t a1 = *(const uint32_t*)(Ab + (row + 8) * 64 + k0 + kq4);
                uint32_t a2 = *(const uint32_t*)(Ab + row * 64 + k0 + kq4 + 16);
                uint32_t a3 = *(const uint32_t*)(Ab + (row + 8) * 64 + k0 + kq4 + 16);
#pragma unroll
                for (int nt = 0; nt < 8; ++nt) {
                    uint32_t b0 = *(const uint32_t*)(xb + nt * 8 * XS_ROW_B + k0 + kq4);
                    uint32_t b1 = *(const uint32_t*)(xb + nt * 8 * XS_ROW_B + k0 + kq4 + 16);
                    mma_e4m3(acc[nt], a0, a1, a2, a3, b0, b1);
                }
            }
        }
        const int fstrip = is9 ? strip : 8 + strip;
        const float* bias_arr = is9 ? g_b9 + strip * 16 : g_b1 + strip * 16;
        const float bias_lo = bias_arr[row];
        const float bias_hi = bias_arr[row + 8];
#pragma unroll
        for (int nt = 0; nt < 8; ++nt)
#pragma unroll
            for (int j = 0; j < 4; ++j) {
                const int ch = row + ((j >= 2) ? 8 : 0);
                const int nl = half * 64 + nt * 8 + (lane & 3) * 2 + (j & 1);
                const int tt = nl >> 5, v = nl & 31;
                if (v < 25)
                    fT[(fstrip * 25 + v) * FT_K + ch * 4 + tt] =
                        __float2bfloat16(acc[nt][j] + ((j >= 2) ? bias_hi : bias_lo));
            }
    }
    __syncthreads();

    // gram: 450 workers = 9 pairs x 25 cells x 2 k-halves (k=32 each)
    if (tid < 450) {
        const int pair = tid / 50, rem = tid % 50;
        const int kh = rem / 25, cell = rem % 25;
        const int v0 = (cell / 5) * 5, w0 = (cell % 5) * 5;
        int br1, gi, gj;
        if (pair < 4) { br1 = 2 * pair;           gi = c_gi9[pair];      gj = c_gj9[pair]; }
        else          { br1 = 8 + 2 * (pair - 4); gi = c_gi1[pair - 4];  gj = c_gj1[pair - 4]; }
        const __nv_bfloat16* f1 = fT + (size_t)(br1 * 25 + v0) * FT_K + kh * 32;
        const __nv_bfloat16* f2 = fT + (size_t)((br1 + 1) * 25 + w0) * FT_K + kh * 32;
        ull g[5][5];
#pragma unroll
        for (int r = 0; r < 5; ++r)
#pragma unroll
            for (int s = 0; s < 5; ++s) g[r][s] = 0ULL;
        for (int kp = 0; kp < 16; ++kp) {
            ull a[5], b[5];
#pragma unroll
            for (int r = 0; r < 5; ++r) {
                float2 fa = __bfloat1622float2(*(const __nv_bfloat162*)(f1 + r * FT_K + kp * 2));
                a[r] = pack2(fa.x, fa.y);
            }
#pragma unroll
            for (int s = 0; s < 5; ++s) {
                float2 fb = __bfloat1622float2(*(const __nv_bfloat162*)(f2 + s * FT_K + kp * 2));
                b[s] = pack2(fb.x, fb.y);
            }
#pragma unroll
            for (int r = 0; r < 5; ++r)
#pragma unroll
                for (int s = 0; s < 5; ++s) fma2(g[r][s], a[r], b[s]);
        }
        float* dst = g_Gram + ((size_t)(n * 3 + gi) * 3 + gj) * 625;
#pragma unroll
        for (int r = 0; r < 5; ++r)
#pragma unroll
            for (int s = 0; s < 5; ++s) {
                float2 f = unpack2(g[r][s]);
                atomicAdd(&dst[(v0 + r) * 25 + (w0 + s)], f.x + f.y);
            }
    }
}

// ---------------- kernel 2: softmax + combine into A1 ----------------------
__global__ void smx_kernel(const float* __restrict__ weights) {
    const int n = blockIdx.x, i = blockIdx.y, w = threadIdx.x;
    if (w >= 25) return;
    const float INV = 1.f / 4096.f / 256.f;   // /256: fp8 x16 feature scale, squared
    const float wj[3] = {weights[5], weights[6], weights[7]};
    float a1[25];
#pragma unroll
    for (int v = 0; v < 25; ++v) a1[v] = g_Acomb[v * 25 + w];
    for (int j = 0; j < 3; ++j) {
        const float* gb = g_Gram + ((size_t)(n * 3 + i) * 3 + j) * 625 + w;
        float m = -1e30f;
        for (int v = 0; v < 25; ++v) m = fmaxf(m, gb[v * 25] * INV);
        float s = 0.f;
        for (int v = 0; v < 25; ++v) s += expf(gb[v * 25] * INV - m);
        float inv = wj[j] / s;
        for (int v = 0; v < 25; ++v) a1[v] += inv * expf(gb[v * 25] * INV - m);
    }
    float* out = g_A1 + (size_t)(n * 3 + i) * 625 + w;
    for (int v = 0; v < 25; ++v) out[v * 25] = a1[v];
}

// ---------------- kernel 3: fin2 (R12-verified) ----------------------------
#define F2_U    0
#define F2_XS   20160
#define F2_A1   26816
#define SMEM_F2 115072

__global__ void __launch_bounds__(512, 2) fin2_kernel(const float* __restrict__ x,
                                                      float* __restrict__ out) {
    extern __shared__ float sm[];
    float* U  = sm + F2_U;          // stride 105
    float* xs = sm + F2_XS;         // stride 104 (104%32=8 -> B-frag bijection)
    ull* A1u  = (ull*)(sm + F2_A1); // [i*25+v][13 wp]
    const int tb = blockIdx.x, nb = blockIdx.y, tid = threadIdx.x;
    const int warp = tid >> 5, lane = tid & 31;

    for (int idx = tid; idx < 64 * 104; idx += 512) {
        int c = idx / 104, j = idx % 104;
        xs[idx] = (j < 100)
            ? tf32r(x[((size_t)(nb * 64 + c)) * 6400 + tb * 100 + j]) : 0.f;
    }
    for (int idx = tid; idx < 975; idx += 512) {
        int wp = idx % 13, r = idx / 13;
        const float* a = g_A1 + (size_t)nb * 1875 + (r / 25) * 625 + (r % 25) * 25;
        float lo = a[2 * wp];
        float hi = (2 * wp + 1 < 25) ? a[2 * wp + 1] : 0.f;
        A1u[idx] = pack2(lo, hi);
    }
    __syncthreads();

    const uint32_t* xsu = (const uint32_t*)xs;
    const float4* AH4 = (const float4*)g_AfH;
    for (int jj = 0; jj < 2; ++jj) {
        if (jj == 1 && warp >= 8) break;
        const int sj = jj ? 16 + warp : warp;
        if (sj >= 24) continue;
        const int strip = sj >> 1, nh = sj & 1;
        const int nt0 = nh * 6;
        float acc[7][4];
#pragma unroll
        for (int a = 0; a < 7; ++a)
#pragma unroll
            for (int b = 0; b < 4; ++b) acc[a][b] = 0.f;
#pragma unroll
        for (int kt = 0; kt < 8; ++kt) {
            float4 ah = AH4[(strip * 8 + kt) * 32 + lane];
            const uint32_t* xb0 = xsu + (8 * kt + (lane & 3)) * 104 + (lane >> 2);
            const uint32_t* xb1 = xb0 + 4 * 104;
#pragma unroll
            for (int nt = 0; nt < 7; ++nt) {
                uint32_t b0 = xb0[(nt0 + nt) * 8];
                uint32_t b1 = xb1[(nt0 + nt) * 8];
                mma_tf32(acc[nt], ah, b0, b1);
            }
        }
        // D-frag store: j&2 -> row+8, j&1 -> col+1 (R7-verified)
#pragma unroll
        for (int nt = 0; nt < 7; ++nt)
#pragma unroll
            for (int j = 0; j < 4; ++j) {
                int r = 16 * strip + (lane >> 2) + ((j & 2) ? 8 : 0);
                int col = (nt0 + nt) * 8 + 2 * (lane & 3) + (j & 1);
                U[r * 105 + col] = acc[nt][j];
            }
    }
    __syncthreads();

    {
        const int t = tid >> 7, o = (tid >> 1) & 63, wh = tid & 1;
        const int wp0 = wh * 6;
        ull acc[7];
#pragma unroll
        for (int wp = 0; wp < 7; ++wp) acc[wp] = 0ULL;
#pragma unroll
        for (int i = 0; i < 3; ++i) {
            const float* Up = U + (i * 64 + o) * 105 + t * 25;
            const ull* Ap = A1u + i * 325;
#pragma unroll
            for (int v = 0; v < 25; ++v) {
                float u = Up[v];
                ull uu = pack2(u, u);
                const ull* a = Ap + v * 13 + wp0;
#pragma unroll
                for (int wp = 0; wp < 7; ++wp) fma2(acc[wp], uu, a[wp]);
            }
        }
        const float bias = g_bd2[o];
        const size_t base = ((size_t)(nb * 64 + o)) * 6400 + (size_t)(tb * 4 + t) * 25;
#pragma unroll
        for (int wp = 0; wp < 7; ++wp) {
            float2 f = unpack2(acc[wp]);
            int w = 2 * (wp0 + wp);
            out[base + w] = fmaxf(f.x + bias + x[base + w], 0.f);
            if (w + 1 < 25)
                out[base + w + 1] = fmaxf(f.y + bias + x[base + w + 1], 0.f);
        }
    }
}

// ---------------- launch ----------------------------------------------------
extern "C" void kernel_launch(void* const* d_in, const int* in_sizes, int n_in,
                              void* d_out, int out_size) {
    const float* x       = (const float*)d_in[0];
    const float* weights = (const float*)d_in[1];
    const float* A       = (const float*)d_in[2];
    const float* Wa      = (const float*)d_in[3];
    const float* ba      = (const float*)d_in[4];
    const float* Wb      = (const float*)d_in[5];
    const float* bb      = (const float*)d_in[6];
    const float* Wd      = (const float*)d_in[7];
    const float* bd      = (const float*)d_in[8];
    const float* WT1     = (const float*)d_in[9];
    const float* bT1     = (const float*)d_in[10];
    const float* WT2     = (const float*)d_in[11];
    const float* bT2     = (const float*)d_in[12];
    const float* WST11   = (const float*)d_in[13];
    const float* bST11   = (const float*)d_in[14];
    const float* WST12   = (const float*)d_in[15];
    const float* bST12   = (const float*)d_in[16];
    const float* bn_g    = (const float*)d_in[17];
    const float* bn_b    = (const float*)d_in[18];
    const float* bn_m    = (const float*)d_in[19];
    const float* bn_v    = (const float*)d_in[20];
    float* out = (float*)d_out;

    cudaFuncSetAttribute(convm_kernel, cudaFuncAttributeMaxDynamicSharedMemorySize, SMEM_CONV);
    cudaFuncSetAttribute(fin2_kernel,  cudaFuncAttributeMaxDynamicSharedMemorySize, SMEM_F2);

    void* gram_ptr = nullptr;
    cudaGetSymbolAddress(&gram_ptr, g_Gram);

    prepA_kernel<<<1, 640>>>(weights, A, ba, bb, bT1, bT2, bST11, bST12,
                             bd, bn_g, bn_b, bn_m, bn_v);
    prepW_kernel<<<64, 256>>>(Wa, Wb, WT1, WT2, WST11, WST12, Wd, bn_g, bn_v);
    cudaMemsetAsync(gram_ptr, 0, sizeof(float) * 64 * 9 * 625);
    convm_kernel<<<dim3(TT / 4, NB), 512, SMEM_CONV>>>(x);
    smx_kernel<<<dim3(NB, 3), 32>>>(weights);
    fin2_kernel<<<dim3(TT / 4, NB), 512, SMEM_F2>>>(x, out);
}

// round 15
// speedup vs baseline: 1.6941x; 1.1329x over previous
#include <cuda_runtime.h>
#include <cuda_bf16.h>
#include <cstdint>

#define NB   64
#define CC   64
#define TT   256
#define VV   25

typedef unsigned long long ull;

// ---------------- scratch (static device memory) ----------------
__device__ __align__(16) uint8_t g_W9q[9 * 128 * 64];  // [tap][ch][cin] e4m3, x16
__device__ __align__(16) uint8_t g_W1q[160 * 64];      // [ch][cin] e4m3, x16
__device__ float g_b9[128];                            // x16
__device__ float g_b1[160];                            // x16
__device__ float g_Acomb[625];
__device__ float g_Gram[64 * 9 * 625];                 // x256
__device__ float g_A1[64 * 3 * 625];
// tf32 A-fragments of WdS^stacked [192 x 64]: [12 strip][8 kt][32 lane][4]
__device__ __align__(16) float g_AfH[12288];
__device__ float g_bd2[64];

// branch tables
__constant__ int c_i9[8]  = {0,0,1,1,1,1,2,2};
__constant__ int c_s9[8]  = {0,1,0,1,2,3,0,1};
__constant__ int c_i1[10] = {0,0,0,0,1,1,2,2,2,2};
__constant__ int c_s1[10] = {0,1,2,3,0,1,0,1,2,3};
__constant__ int c_gi9[4] = {0,1,1,2};
__constant__ int c_gj9[4] = {1,1,2,1};
__constant__ int c_gi1[5] = {0,0,1,2,2};
__constant__ int c_gj1[5] = {0,2,0,0,2};

// ---------------- helpers ----------------
__device__ __forceinline__ ull pack2(float lo, float hi) {
    ull r; asm("mov.b64 %0, {%1,%2};" : "=l"(r) : "f"(lo), "f"(hi)); return r;
}
__device__ __forceinline__ void fma2(ull& d, ull a, ull b) {
    asm("fma.rn.f32x2 %0, %1, %2, %0;" : "+l"(d) : "l"(a), "l"(b));
}
__device__ __forceinline__ float2 unpack2(ull p) {
    float2 f; asm("mov.b64 {%0,%1}, %2;" : "=f"(f.x), "=f"(f.y) : "l"(p)); return f;
}
__device__ __forceinline__ float tf32r(float f) {
    uint32_t u;
    asm("cvt.rn.tf32.f32 %0, %1;" : "=r"(u) : "f"(f));
    return __uint_as_float(u);
}
__device__ __forceinline__ uint16_t f2e4m3x2(float hi, float lo) {
    uint16_t u;
    asm("cvt.rn.satfinite.e4m3x2.f32 %0, %1, %2;" : "=h"(u) : "f"(hi), "f"(lo));
    return u;
}
__device__ __forceinline__ void mma_e4m3(float* d, uint32_t a0, uint32_t a1,
                                         uint32_t a2, uint32_t a3,
                                         uint32_t b0, uint32_t b1) {
    asm volatile(
        "mma.sync.aligned.m16n8k32.row.col.f32.e4m3.e4m3.f32 "
        "{%0,%1,%2,%3}, {%4,%5,%6,%7}, {%8,%9}, {%0,%1,%2,%3};"
        : "+f"(d[0]), "+f"(d[1]), "+f"(d[2]), "+f"(d[3])
        : "r"(a0), "r"(a1), "r"(a2), "r"(a3), "r"(b0), "r"(b1));
}
__device__ __forceinline__ void mma_tf32(float* d, float4 a, uint32_t b0, uint32_t b1) {
    asm volatile(
        "mma.sync.aligned.m16n8k8.row.col.f32.tf32.tf32.f32 "
        "{%0,%1,%2,%3}, {%4,%5,%6,%7}, {%8,%9}, {%0,%1,%2,%3};"
        : "+f"(d[0]), "+f"(d[1]), "+f"(d[2]), "+f"(d[3])
        : "r"(__float_as_uint(a.x)), "r"(__float_as_uint(a.y)),
          "r"(__float_as_uint(a.z)), "r"(__float_as_uint(a.w)),
          "r"(b0), "r"(b1));
}

// ---------------- kernel 0a: prepA ----------------
__global__ void prepA_kernel(const float* __restrict__ weights, const float* __restrict__ A,
                             const float* __restrict__ ba, const float* __restrict__ bb,
                             const float* __restrict__ bT1, const float* __restrict__ bT2,
                             const float* __restrict__ bST11, const float* __restrict__ bST12,
                             const float* __restrict__ bd,
                             const float* __restrict__ gamma, const float* __restrict__ beta,
                             const float* __restrict__ mean, const float* __restrict__ var) {
    __shared__ float sA[625], sA4[625];
    const int tid = threadIdx.x;
    if (tid < 625) {
        float a = A[tid];
        sA[tid] = a;
        int v = tid / 25, w = tid % 25;
        float a2 = a * a;  // elementwise Chebyshev (torch.pow semantics)
        sA4[tid] = 8.f * a2 * a2 - 8.f * a2 + (v == w ? 1.f : 0.f);
    }
    __syncthreads();
    if (tid < 25) {
        const int w = tid;
        float w0 = weights[0], w1 = weights[1];
        float m = -1e30f;
        for (int v = 0; v < 25; ++v) m = fmaxf(m, sA4[v*25+w] * 0.04f);
        float ssum = 0.f;
        for (int v = 0; v < 25; ++v) ssum += expf(sA4[v*25+w] * 0.04f - m);
        float inv = 1.f / ssum;
        for (int v = 0; v < 25; ++v)
            g_Acomb[v*25+w] = w0 * sA[v*25+w] + w1 * expf(sA4[v*25+w] * 0.04f - m) * inv;
    }
    for (int idx = tid; idx < 128; idx += blockDim.x) {
        int g = idx >> 4, c = idx & 15;
        int i = c_i9[g], s = c_s9[g];
        const float* B = (s == 0) ? bT1 : (s == 1) ? bT2 : (s == 2) ? bST11 : bST12;
        g_b9[idx] = 16.f * B[i*16 + c];
    }
    for (int idx = tid; idx < 160; idx += blockDim.x) {
        int g = idx >> 4, c = idx & 15;
        int i = c_i1[g], s = c_s1[g];
        const float* B = (s == 0) ? ba : (s == 1) ? bb : (s == 2) ? bST11 : bST12;
        g_b1[idx] = 16.f * B[i*16 + c];
    }
    for (int o = tid; o < 64; o += blockDim.x) {
        float sc = gamma[o] * rsqrtf(var[o] + 1e-5f);
        g_bd2[o] = (bd[o] + bd[64 + o] + bd[128 + o] - mean[o]) * sc + beta[o];
    }
}

// ---------------- kernel 0b: prepW ----------------
__global__ void prepW_kernel(const float* __restrict__ Wa, const float* __restrict__ Wb,
                             const float* __restrict__ WT1, const float* __restrict__ WT2,
                             const float* __restrict__ WST11, const float* __restrict__ WST12,
                             const float* __restrict__ Wd,
                             const float* __restrict__ gamma, const float* __restrict__ var) {
    const int gtid = blockIdx.x * blockDim.x + threadIdx.x;
    const int gsz = gridDim.x * blockDim.x;
    for (int idx = gtid; idx < 9 * 128 * 32; idx += gsz) {
        int tap = idx / 4096, r = idx % 4096;
        int m = r / 32, cp = r % 32;
        int g = m >> 4;
        int i = c_i9[g], s = c_s9[g];
        const float* W = (s == 0) ? WT1 : (s == 1) ? WT2 : (s == 2) ? WST11 : WST12;
        const float* base = W + ((size_t)(i*16 + (m & 15))*64) * 9 + tap;
        float w0 = 16.f * base[(2*cp) * 9];
        float w1 = 16.f * base[(2*cp + 1) * 9];
        ((uint16_t*)g_W9q)[idx] = f2e4m3x2(w1, w0);
    }
    for (int idx = gtid; idx < 160 * 32; idx += gsz) {
        int m = idx / 32, cp = idx % 32;
        int g = m >> 4;
        int i = c_i1[g], s = c_s1[g];
        float w0, w1;
        if (s == 0)      { w0 = Wa[(i*16+(m&15))*64 + 2*cp];      w1 = Wa[(i*16+(m&15))*64 + 2*cp+1]; }
        else if (s == 1) { w0 = Wb[(i*16+(m&15))*64 + 2*cp];      w1 = Wb[(i*16+(m&15))*64 + 2*cp+1]; }
        else if (s == 2) { w0 = WST11[((i*16+(m&15))*64 + 2*cp)*9 + 4];
                           w1 = WST11[((i*16+(m&15))*64 + 2*cp+1)*9 + 4]; }
        else             { w0 = WST12[((i*16+(m&15))*64 + 2*cp)*9 + 4];
                           w1 = WST12[((i*16+(m&15))*64 + 2*cp+1)*9 + 4]; }
        ((uint16_t*)g_W1q)[idx] = f2e4m3x2(16.f * w1, 16.f * w0);
    }
    // A-frag (R7-verified): j&1 -> row+8, j&2 -> col+4
    for (int idx = gtid; idx < 12288; idx += gsz) {
        int j = idx & 3, lane = (idx >> 2) & 31, kt = (idx >> 7) & 7, s = idx >> 10;
        int row = (lane >> 2) + ((j & 1) ? 8 : 0);
        int col = (lane & 3) + ((j & 2) ? 4 : 0);
        int m = 16 * s + row, c = 8 * kt + col;
        int i = m >> 6, o = m & 63;
        float sc = gamma[o] * rsqrtf(var[o] + 1e-5f);
        g_AfH[idx] = tf32r(Wd[(i * 64 + o) * 64 + c] * sc);
    }
}

// ---------------- kernel 1: unified conv (fp8 mma, 8t) + fused gram --------
// xs: fp8 [512 rows (16 tsl x 32 v)][144B rows, 64 valid cin]
// fT: [18 br][25 v][130 kpad] bf16 (x16), k = (ch%16)*8 + tt
#define XS_ROW_B    144
#define XS_BYTES    (512 * XS_ROW_B)            // 73728
#define FT_K        130
#define FT_BF16     (18 * 25 * FT_K)            // 58500
#define SMEM_CONV   (XS_BYTES + FT_BF16 * 2)    // 190728 B

__global__ void __launch_bounds__(512, 1) convm_kernel(const float* __restrict__ x) {
    extern __shared__ uint8_t smu[];
    uint8_t* xs = smu;
    __nv_bfloat16* fT = (__nv_bfloat16*)(smu + XS_BYTES);
    const int n = blockIdx.y, t0 = blockIdx.x * 8;
    const int tid = threadIdx.x, warp = tid >> 5, lane = tid & 31;

    {
        const float* xn = x + (size_t)n * (CC * TT * VV);
        for (int idx = tid; idx < 64 * 16 * 25; idx += 512) {
            int cin = idx / 400, r = idx % 400;
            int tsl = r / 25, v = r % 25;
            int t = t0 - 4 + tsl;
            float val = (t >= 0 && t < TT) ? xn[(cin * TT + t) * VV + v] : 0.f;
            xs[(tsl * 32 + v) * XS_ROW_B + cin] = (uint8_t)f2e4m3x2(0.f, val);
        }
    }
    __syncthreads();

    const int row = lane >> 2;
    const int kq4 = (lane & 3) * 4;
    float acc[16][4];

    for (int ph = 0; ph < 3; ++ph) {
        if (ph == 2 && warp >= 4) break;
        int strip, half, is9;
        if (ph == 0) { strip = warp >> 1; half = warp & 1; is9 = 1; }
        else {
            int c1 = (ph == 1) ? warp : 16 + warp;
            strip = c1 >> 1; half = c1 & 1; is9 = 0;
        }
#pragma unroll
        for (int a = 0; a < 16; ++a)
#pragma unroll
            for (int b = 0; b < 4; ++b) acc[a][b] = 0.f;

        const int ntaps = is9 ? 9 : 1;
        for (int jt = 0; jt < ntaps; ++jt) {
            const int tap = is9 ? jt : 4;
            const uint8_t* Ab = is9 ? g_W9q + (size_t)(tap * 128 + strip * 16) * 64
                                    : g_W1q + (size_t)strip * 16 * 64;
            const uint8_t* xb = xs + (size_t)(tap * 32 + half * 128 + row) * XS_ROW_B;
#pragma unroll
            for (int k0 = 0; k0 < 64; k0 += 32) {
                uint32_t a0 = *(const uint32_t*)(Ab + row * 64 + k0 + kq4);
                uint32_t a1 = *(const uint32_t*)(Ab + (row + 8) * 64 + k0 + kq4);
                uint32_t a2 = *(const uint32_t*)(Ab + row * 64 + k0 + kq4 + 16);
                uint32_t a3 = *(const uint32_t*)(Ab + (row + 8) * 64 + k0 + kq4 + 16);
#pragma unroll
                for (int nt = 0; nt < 16; ++nt) {
                    uint32_t b0 = *(const uint32_t*)(xb + nt * 8 * XS_ROW_B + k0 + kq4);
                    uint32_t b1 = *(const uint32_t*)(xb + nt * 8 * XS_ROW_B + k0 + kq4 + 16);
                    mma_e4m3(acc[nt], a0, a1, a2, a3, b0, b1);
                }
            }
        }
        const int fstrip = is9 ? strip : 8 + strip;
        const float* bias_arr = is9 ? g_b9 + strip * 16 : g_b1 + strip * 16;
        const float bias_lo = bias_arr[row];
        const float bias_hi = bias_arr[row + 8];
#pragma unroll
        for (int nt = 0; nt < 16; ++nt)
#pragma unroll
            for (int j = 0; j < 4; ++j) {
                const int ch = row + ((j >= 2) ? 8 : 0);
                const int nl = half * 128 + nt * 8 + (lane & 3) * 2 + (j & 1);
                const int tt = nl >> 5, v = nl & 31;
                if (v < 25)
                    fT[(fstrip * 25 + v) * FT_K + ch * 8 + tt] =
                        __float2bfloat16(acc[nt][j] + ((j >= 2) ? bias_hi : bias_lo));
            }
    }
    __syncthreads();

    // gram: 450 workers = 9 pairs x 25 cells x 2 k-halves (k=64 each)
    if (tid < 450) {
        const int pair = tid / 50, rem = tid % 50;
        const int kh = rem / 25, cell = rem % 25;
        const int v0 = (cell / 5) * 5, w0 = (cell % 5) * 5;
        int br1, gi, gj;
        if (pair < 4) { br1 = 2 * pair;           gi = c_gi9[pair];      gj = c_gj9[pair]; }
        else          { br1 = 8 + 2 * (pair - 4); gi = c_gi1[pair - 4];  gj = c_gj1[pair - 4]; }
        const __nv_bfloat16* f1 = fT + (size_t)(br1 * 25 + v0) * FT_K + kh * 64;
        const __nv_bfloat16* f2 = fT + (size_t)((br1 + 1) * 25 + w0) * FT_K + kh * 64;
        ull g[5][5];
#pragma unroll
        for (int r = 0; r < 5; ++r)
#pragma unroll
            for (int s = 0; s < 5; ++s) g[r][s] = 0ULL;
        for (int kp = 0; kp < 32; ++kp) {
            ull a[5], b[5];
#pragma unroll
            for (int r = 0; r < 5; ++r) {
                float2 fa = __bfloat1622float2(*(const __nv_bfloat162*)(f1 + r * FT_K + kp * 2));
                a[r] = pack2(fa.x, fa.y);
            }
#pragma unroll
            for (int s = 0; s < 5; ++s) {
                float2 fb = __bfloat1622float2(*(const __nv_bfloat162*)(f2 + s * FT_K + kp * 2));
                b[s] = pack2(fb.x, fb.y);
            }
#pragma unroll
            for (int r = 0; r < 5; ++r)
#pragma unroll
                for (int s = 0; s < 5; ++s) fma2(g[r][s], a[r], b[s]);
        }
        float* dst = g_Gram + ((size_t)(n * 3 + gi) * 3 + gj) * 625;
#pragma unroll
        for (int r = 0; r < 5; ++r)
#pragma unroll
            for (int s = 0; s < 5; ++s) {
                float2 f = unpack2(g[r][s]);
                atomicAdd(&dst[(v0 + r) * 25 + (w0 + s)], f.x + f.y);
            }
    }
}

// ---------------- kernel 2: softmax + combine into A1 ----------------------
__global__ void smx_kernel(const float* __restrict__ weights) {
    const int n = blockIdx.x, i = blockIdx.y, w = threadIdx.x;
    if (w >= 25) return;
    const float INV = 1.f / 4096.f / 256.f;   // /256: fp8 x16 feature scale, squared
    const float wj[3] = {weights[5], weights[6], weights[7]};
    float a1[25];
#pragma unroll
    for (int v = 0; v < 25; ++v) a1[v] = g_Acomb[v * 25 + w];
    for (int j = 0; j < 3; ++j) {
        const float* gb = g_Gram + ((size_t)(n * 3 + i) * 3 + j) * 625 + w;
        float m = -1e30f;
        for (int v = 0; v < 25; ++v) m = fmaxf(m, gb[v * 25] * INV);
        float s = 0.f;
        for (int v = 0; v < 25; ++v) s += expf(gb[v * 25] * INV - m);
        float inv = wj[j] / s;
        for (int v = 0; v < 25; ++v) a1[v] += inv * expf(gb[v * 25] * INV - m);
    }
    float* out = g_A1 + (size_t)(n * 3 + i) * 625 + w;
    for (int v = 0; v < 25; ++v) out[v * 25] = a1[v];
}

// ---------------- kernel 3: fin2 (residual from smem) ----------------------
#define F2_U    0
#define F2_XS   20160
#define F2_A1   26816
#define SMEM_F2 115072

__global__ void __launch_bounds__(512, 2) fin2_kernel(const float* __restrict__ x,
                                                      float* __restrict__ out) {
    extern __shared__ float sm[];
    float* U  = sm + F2_U;          // stride 105
    float* xs = sm + F2_XS;         // stride 104 (104%32=8 -> B-frag bijection)
    ull* A1u  = (ull*)(sm + F2_A1); // [i*25+v][13 wp]
    const int tb = blockIdx.x, nb = blockIdx.y, tid = threadIdx.x;
    const int warp = tid >> 5, lane = tid & 31;

    for (int idx = tid; idx < 64 * 104; idx += 512) {
        int c = idx / 104, j = idx % 104;
        xs[idx] = (j < 100)
            ? tf32r(x[((size_t)(nb * 64 + c)) * 6400 + tb * 100 + j]) : 0.f;
    }
    for (int idx = tid; idx < 975; idx += 512) {
        int wp = idx % 13, r = idx / 13;
        const float* a = g_A1 + (size_t)nb * 1875 + (r / 25) * 625 + (r % 25) * 25;
        float lo = a[2 * wp];
        float hi = (2 * wp + 1 < 25) ? a[2 * wp + 1] : 0.f;
        A1u[idx] = pack2(lo, hi);
    }
    __syncthreads();

    const uint32_t* xsu = (const uint32_t*)xs;
    const float4* AH4 = (const float4*)g_AfH;
    for (int jj = 0; jj < 2; ++jj) {
        if (jj == 1 && warp >= 8) break;
        const int sj = jj ? 16 + warp : warp;
        if (sj >= 24) continue;
        const int strip = sj >> 1, nh = sj & 1;
        const int nt0 = nh * 6;
        float acc[7][4];
#pragma unroll
        for (int a = 0; a < 7; ++a)
#pragma unroll
            for (int b = 0; b < 4; ++b) acc[a][b] = 0.f;
#pragma unroll
        for (int kt = 0; kt < 8; ++kt) {
            float4 ah = AH4[(strip * 8 + kt) * 32 + lane];
            const uint32_t* xb0 = xsu + (8 * kt + (lane & 3)) * 104 + (lane >> 2);
            const uint32_t* xb1 = xb0 + 4 * 104;
#pragma unroll
            for (int nt = 0; nt < 7; ++nt) {
                uint32_t b0 = xb0[(nt0 + nt) * 8];
                uint32_t b1 = xb1[(nt0 + nt) * 8];
                mma_tf32(acc[nt], ah, b0, b1);
            }
        }
        // D-frag store: j&2 -> row+8, j&1 -> col+1 (R7-verified)
#pragma unroll
        for (int nt = 0; nt < 7; ++nt)
#pragma unroll
            for (int j = 0; j < 4; ++j) {
                int r = 16 * strip + (lane >> 2) + ((j & 2) ? 8 : 0);
                int col = (nt0 + nt) * 8 + 2 * (lane & 3) + (j & 1);
                U[r * 105 + col] = acc[nt][j];
            }
    }
    __syncthreads();

    {
        const int t = tid >> 7, o = (tid >> 1) & 63, wh = tid & 1;
        const int wp0 = wh * 6;
        ull acc[7];
#pragma unroll
        for (int wp = 0; wp < 7; ++wp) acc[wp] = 0ULL;
#pragma unroll
        for (int i = 0; i < 3; ++i) {
            const float* Up = U + (i * 64 + o) * 105 + t * 25;
            const ull* Ap = A1u + i * 325;
#pragma unroll
            for (int v = 0; v < 25; ++v) {
                float u = Up[v];
                ull uu = pack2(u, u);
                const ull* a = Ap + v * 13 + wp0;
#pragma unroll
                for (int wp = 0; wp < 7; ++wp) fma2(acc[wp], uu, a[wp]);
            }
        }
        const float bias = g_bd2[o];
        const float* xrow = xs + o * 104 + t * 25;   // residual from smem (tf32 x)
        const size_t base = ((size_t)(nb * 64 + o)) * 6400 + (size_t)(tb * 4 + t) * 25;
#pragma unroll
        for (int wp = 0; wp < 7; ++wp) {
            float2 f = unpack2(acc[wp]);
            int w = 2 * (wp0 + wp);
            out[base + w] = fmaxf(f.x + bias + xrow[w], 0.f);
            if (w + 1 < 25)
                out[base + w + 1] = fmaxf(f.y + bias + xrow[w + 1], 0.f);
        }
    }
}

// ---------------- launch ----------------------------------------------------
extern "C" void kernel_launch(void* const* d_in, const int* in_sizes, int n_in,
                              void* d_out, int out_size) {
    const float* x       = (const float*)d_in[0];
    const float* weights = (const float*)d_in[1];
    const float* A       = (const float*)d_in[2];
    const float* Wa      = (const float*)d_in[3];
    const float* ba      = (const float*)d_in[4];
    const float* Wb      = (const float*)d_in[5];
    const float* bb      = (const float*)d_in[6];
    const float* Wd      = (const float*)d_in[7];
    const float* bd      = (const float*)d_in[8];
    const float* WT1     = (const float*)d_in[9];
    const float* bT1     = (const float*)d_in[10];
    const float* WT2     = (const float*)d_in[11];
    const float* bT2     = (const float*)d_in[12];
    const float* WST11   = (const float*)d_in[13];
    const float* bST11   = (const float*)d_in[14];
    const float* WST12   = (const float*)d_in[15];
    const float* bST12   = (const float*)d_in[16];
    const float* bn_g    = (const float*)d_in[17];
    const float* bn_b    = (const float*)d_in[18];
    const float* bn_m    = (const float*)d_in[19];
    const float* bn_v    = (const float*)d_in[20];
    float* out = (float*)d_out;

    cudaFuncSetAttribute(convm_kernel, cudaFuncAttributeMaxDynamicSharedMemorySize, SMEM_CONV);
    cudaFuncSetAttribute(fin2_kernel,  cudaFuncAttributeMaxDynamicSharedMemorySize, SMEM_F2);

    void* gram_ptr = nullptr;
    cudaGetSymbolAddress(&gram_ptr, g_Gram);

    prepA_kernel<<<1, 640>>>(weights, A, ba, bb, bT1, bT2, bST11, bST12,
                             bd, bn_g, bn_b, bn_m, bn_v);
    prepW_kernel<<<64, 256>>>(Wa, Wb, WT1, WT2, WST11, WST12, Wd, bn_g, bn_v);
    cudaMemsetAsync(gram_ptr, 0, sizeof(float) * 64 * 9 * 625);
    convm_kernel<<<dim3(TT / 8, NB), 512, SMEM_CONV>>>(x);
    smx_kernel<<<dim3(NB, 3), 32>>>(weights);
    fin2_kernel<<<dim3(TT / 4, NB), 512, SMEM_F2>>>(x, out);
}

// round 16
// speedup vs baseline: 1.7944x; 1.0592x over previous
#include <cuda_runtime.h>
#include <cuda_bf16.h>
#include <cstdint>

#define NB   64
#define CC   64
#define TT   256
#define VV   25

typedef unsigned long long ull;

// ---------------- scratch (static device memory) ----------------
// Pre-packed e4m3 A-fragments (x16 scale), lane-ordered uint4:
//   g_W9f[((tap*8 + strip)*2 + k0i)*32 + lane] = {a0,a1,a2,a3}
__device__ __align__(16) uint4 g_W9f[9 * 8 * 2 * 32];
__device__ __align__(16) uint4 g_W1f[10 * 2 * 32];
__device__ float g_b9[128];                            // x16
__device__ float g_b1[160];                            // x16
__device__ float g_Acomb[625];
__device__ float g_Gram[64 * 9 * 625];                 // x256
__device__ float g_A1[64 * 3 * 625];
// tf32 A-fragments of WdS^stacked [192 x 64]: [12 strip][8 kt][32 lane][4]
__device__ __align__(16) float g_AfH[12288];
__device__ float g_bd2[64];

// branch tables
__constant__ int c_i9[8]  = {0,0,1,1,1,1,2,2};
__constant__ int c_s9[8]  = {0,1,0,1,2,3,0,1};
__constant__ int c_i1[10] = {0,0,0,0,1,1,2,2,2,2};
__constant__ int c_s1[10] = {0,1,2,3,0,1,0,1,2,3};
__constant__ int c_gi9[4] = {0,1,1,2};
__constant__ int c_gj9[4] = {1,1,2,1};
__constant__ int c_gi1[5] = {0,0,1,2,2};
__constant__ int c_gj1[5] = {0,2,0,0,2};

// ---------------- helpers ----------------
__device__ __forceinline__ ull pack2(float lo, float hi) {
    ull r; asm("mov.b64 %0, {%1,%2};" : "=l"(r) : "f"(lo), "f"(hi)); return r;
}
__device__ __forceinline__ void fma2(ull& d, ull a, ull b) {
    asm("fma.rn.f32x2 %0, %1, %2, %0;" : "+l"(d) : "l"(a), "l"(b));
}
__device__ __forceinline__ float2 unpack2(ull p) {
    float2 f; asm("mov.b64 {%0,%1}, %2;" : "=f"(f.x), "=f"(f.y) : "l"(p)); return f;
}
__device__ __forceinline__ float tf32r(float f) {
    uint32_t u;
    asm("cvt.rn.tf32.f32 %0, %1;" : "=r"(u) : "f"(f));
    return __uint_as_float(u);
}
__device__ __forceinline__ uint16_t f2e4m3x2(float hi, float lo) {
    uint16_t u;
    asm("cvt.rn.satfinite.e4m3x2.f32 %0, %1, %2;" : "=h"(u) : "f"(hi), "f"(lo));
    return u;
}
__device__ __forceinline__ void mma_e4m3(float* d, uint32_t a0, uint32_t a1,
                                         uint32_t a2, uint32_t a3,
                                         uint32_t b0, uint32_t b1) {
    asm volatile(
        "mma.sync.aligned.m16n8k32.row.col.f32.e4m3.e4m3.f32 "
        "{%0,%1,%2,%3}, {%4,%5,%6,%7}, {%8,%9}, {%0,%1,%2,%3};"
        : "+f"(d[0]), "+f"(d[1]), "+f"(d[2]), "+f"(d[3])
        : "r"(a0), "r"(a1), "r"(a2), "r"(a3), "r"(b0), "r"(b1));
}
__device__ __forceinline__ void mma_tf32(float* d, float4 a, uint32_t b0, uint32_t b1) {
    asm volatile(
        "mma.sync.aligned.m16n8k8.row.col.f32.tf32.tf32.f32 "
        "{%0,%1,%2,%3}, {%4,%5,%6,%7}, {%8,%9}, {%0,%1,%2,%3};"
        : "+f"(d[0]), "+f"(d[1]), "+f"(d[2]), "+f"(d[3])
        : "r"(__float_as_uint(a.x)), "r"(__float_as_uint(a.y)),
          "r"(__float_as_uint(a.z)), "r"(__float_as_uint(a.w)),
          "r"(b0), "r"(b1));
}

// ---------------- kernel 0a: prepA ----------------
__global__ void prepA_kernel(const float* __restrict__ weights, const float* __restrict__ A,
                             const float* __restrict__ ba, const float* __restrict__ bb,
                             const float* __restrict__ bT1, const float* __restrict__ bT2,
                             const float* __restrict__ bST11, const float* __restrict__ bST12,
                             const float* __restrict__ bd,
                             const float* __restrict__ gamma, const float* __restrict__ beta,
                             const float* __restrict__ mean, const float* __restrict__ var) {
    __shared__ float sA[625], sA4[625];
    const int tid = threadIdx.x;
    if (tid < 625) {
        float a = A[tid];
        sA[tid] = a;
        int v = tid / 25, w = tid % 25;
        float a2 = a * a;  // elementwise Chebyshev (torch.pow semantics)
        sA4[tid] = 8.f * a2 * a2 - 8.f * a2 + (v == w ? 1.f : 0.f);
    }
    __syncthreads();
    if (tid < 25) {
        const int w = tid;
        float w0 = weights[0], w1 = weights[1];
        float m = -1e30f;
        for (int v = 0; v < 25; ++v) m = fmaxf(m, sA4[v*25+w] * 0.04f);
        float ssum = 0.f;
        for (int v = 0; v < 25; ++v) ssum += expf(sA4[v*25+w] * 0.04f - m);
        float inv = 1.f / ssum;
        for (int v = 0; v < 25; ++v)
            g_Acomb[v*25+w] = w0 * sA[v*25+w] + w1 * expf(sA4[v*25+w] * 0.04f - m) * inv;
    }
    for (int idx = tid; idx < 128; idx += blockDim.x) {
        int g = idx >> 4, c = idx & 15;
        int i = c_i9[g], s = c_s9[g];
        const float* B = (s == 0) ? bT1 : (s == 1) ? bT2 : (s == 2) ? bST11 : bST12;
        g_b9[idx] = 16.f * B[i*16 + c];
    }
    for (int idx = tid; idx < 160; idx += blockDim.x) {
        int g = idx >> 4, c = idx & 15;
        int i = c_i1[g], s = c_s1[g];
        const float* B = (s == 0) ? ba : (s == 1) ? bb : (s == 2) ? bST11 : bST12;
        g_b1[idx] = 16.f * B[i*16 + c];
    }
    for (int o = tid; o < 64; o += blockDim.x) {
        float sc = gamma[o] * rsqrtf(var[o] + 1e-5f);
        g_bd2[o] = (bd[o] + bd[64 + o] + bd[128 + o] - mean[o]) * sc + beta[o];
    }
}

// ---------------- kernel 0b: prepW ----------------
__global__ void prepW_kernel(const float* __restrict__ Wa, const float* __restrict__ Wb,
                             const float* __restrict__ WT1, const float* __restrict__ WT2,
                             const float* __restrict__ WST11, const float* __restrict__ WST12,
                             const float* __restrict__ Wd,
                             const float* __restrict__ gamma, const float* __restrict__ var) {
    const int gtid = blockIdx.x * blockDim.x + threadIdx.x;
    const int gsz = gridDim.x * blockDim.x;
    // conv9 A-fragments: each u32 = 4 e4m3 bytes of row (ch), cin cin0..cin0+3
    for (int idx = gtid; idx < 9 * 8 * 2 * 32 * 4; idx += gsz) {
        int j = idx & 3, lane = (idx >> 2) & 31, k0i = (idx >> 7) & 1;
        int strip = (idx >> 8) & 7, tap = idx >> 11;
        int row = lane >> 2, kq4 = (lane & 3) * 4;
        int ch = strip * 16 + row + ((j & 1) ? 8 : 0);
        int cin0 = k0i * 32 + kq4 + ((j & 2) ? 16 : 0);
        int g = ch >> 4;
        int i = c_i9[g], s = c_s9[g];
        const float* W = (s == 0) ? WT1 : (s == 1) ? WT2 : (s == 2) ? WST11 : WST12;
        const float* base = W + ((size_t)(i*16 + (ch & 15))*64 + cin0) * 9 + tap;
        uint32_t lo = f2e4m3x2(16.f * base[9],  16.f * base[0]);
        uint32_t hi = f2e4m3x2(16.f * base[27], 16.f * base[18]);
        ((uint32_t*)g_W9f)[idx] = lo | (hi << 16);
    }
    // conv1 A-fragments (center tap for ST branches)
    for (int idx = gtid; idx < 10 * 2 * 32 * 4; idx += gsz) {
        int j = idx & 3, lane = (idx >> 2) & 31, k0i = (idx >> 7) & 1;
        int strip = idx >> 8;
        int row = lane >> 2, kq4 = (lane & 3) * 4;
        int ch = strip * 16 + row + ((j & 1) ? 8 : 0);
        int cin0 = k0i * 32 + kq4 + ((j & 2) ? 16 : 0);
        int g = ch >> 4;
        int i = c_i1[g], s = c_s1[g];
        float w[4];
#pragma unroll
        for (int b = 0; b < 4; ++b) {
            int cin = cin0 + b;
            if (s == 0)      w[b] = Wa[(i*16 + (ch & 15))*64 + cin];
            else if (s == 1) w[b] = Wb[(i*16 + (ch & 15))*64 + cin];
            else if (s == 2) w[b] = WST11[((i*16 + (ch & 15))*64 + cin)*9 + 4];
            else             w[b] = WST12[((i*16 + (ch & 15))*64 + cin)*9 + 4];
        }
        uint32_t lo = f2e4m3x2(16.f * w[1], 16.f * w[0]);
        uint32_t hi = f2e4m3x2(16.f * w[3], 16.f * w[2]);
        ((uint32_t*)g_W1f)[idx] = lo | (hi << 16);
    }
    // A-frag (R7-verified): j&1 -> row+8, j&2 -> col+4
    for (int idx = gtid; idx < 12288; idx += gsz) {
        int j = idx & 3, lane = (idx >> 2) & 31, kt = (idx >> 7) & 7, s = idx >> 10;
        int row = (lane >> 2) + ((j & 1) ? 8 : 0);
        int col = (lane & 3) + ((j & 2) ? 4 : 0);
        int m = 16 * s + row, c = 8 * kt + col;
        int i = m >> 6, o = m & 63;
        float sc = gamma[o] * rsqrtf(var[o] + 1e-5f);
        g_AfH[idx] = tf32r(Wd[(i * 64 + o) * 64 + c] * sc);
    }
}

// ---------------- dummy (shifts ncu -s 5 capture onto convm) ---------------
__global__ void dummy_kernel() {}

// ---------------- kernel 1: unified conv (fp8 mma, 8t) + fused gram --------
#define XS_ROW_B    144
#define XS_BYTES    (512 * XS_ROW_B)            // 73728
#define FT_K        130
#define FT_BF16     (18 * 25 * FT_K)            // 58500
#define SMEM_CONV   (XS_BYTES + FT_BF16 * 2)    // 190728 B

__global__ void __launch_bounds__(512, 1) convm_kernel(const float* __restrict__ x) {
    extern __shared__ uint8_t smu[];
    uint8_t* xs = smu;
    __nv_bfloat16* fT = (__nv_bfloat16*)(smu + XS_BYTES);
    const int n = blockIdx.y, t0 = blockIdx.x * 8;
    const int tid = threadIdx.x, warp = tid >> 5, lane = tid & 31;

    // stage x -> e4m3, 2 cin per u16 store
    {
        const float* xn = x + (size_t)n * (CC * TT * VV);
        for (int idx = tid; idx < 32 * 16 * 25; idx += 512) {
            int cinp = idx / 400, r = idx % 400;
            int tsl = r / 25, v = r % 25;
            int t = t0 - 4 + tsl;
            float v0 = 0.f, v1 = 0.f;
            if (t >= 0 && t < TT) {
                const float* p = xn + ((size_t)(2 * cinp) * TT + t) * VV + v;
                v0 = p[0];
                v1 = p[TT * VV];
            }
            *(uint16_t*)(xs + (tsl * 32 + v) * XS_ROW_B + 2 * cinp) = f2e4m3x2(v1, v0);
        }
    }
    __syncthreads();

    const int row = lane >> 2;
    float acc[16][4];

    for (int ph = 0; ph < 3; ++ph) {
        if (ph == 2 && warp >= 4) break;
        int strip, half, is9;
        if (ph == 0) { strip = warp >> 1; half = warp & 1; is9 = 1; }
        else {
            int c1 = (ph == 1) ? warp : 16 + warp;
            strip = c1 >> 1; half = c1 & 1; is9 = 0;
        }
#pragma unroll
        for (int a = 0; a < 16; ++a)
#pragma unroll
            for (int b = 0; b < 4; ++b) acc[a][b] = 0.f;

        const int kq4 = (lane & 3) * 4;
        const int ntaps = is9 ? 9 : 1;
        for (int jt = 0; jt < ntaps; ++jt) {
            const int tap = is9 ? jt : 4;
            const uint4* Af = is9 ? g_W9f + (size_t)((tap * 8 + strip) * 2) * 32
                                  : g_W1f + (size_t)(strip * 2) * 32;
            const uint8_t* xb = xs + (size_t)(tap * 32 + half * 128 + row) * XS_ROW_B;
#pragma unroll
            for (int k0i = 0; k0i < 2; ++k0i) {
                const uint4 af = Af[k0i * 32 + lane];
                const int k0 = k0i * 32;
#pragma unroll
                for (int nt = 0; nt < 16; ++nt) {
                    uint32_t b0 = *(const uint32_t*)(xb + nt * 8 * XS_ROW_B + k0 + kq4);
                    uint32_t b1 = *(const uint32_t*)(xb + nt * 8 * XS_ROW_B + k0 + kq4 + 16);
                    mma_e4m3(acc[nt], af.x, af.y, af.z, af.w, b0, b1);
                }
            }
        }
        const int fstrip = is9 ? strip : 8 + strip;
        const float* bias_arr = is9 ? g_b9 + strip * 16 : g_b1 + strip * 16;
        const float bias_lo = bias_arr[row];
        const float bias_hi = bias_arr[row + 8];
#pragma unroll
        for (int nt = 0; nt < 16; ++nt)
#pragma unroll
            for (int j = 0; j < 4; ++j) {
                const int ch = row + ((j >= 2) ? 8 : 0);
                const int nl = half * 128 + nt * 8 + (lane & 3) * 2 + (j & 1);
                const int tt = nl >> 5, v = nl & 31;
                if (v < 25)
                    fT[(fstrip * 25 + v) * FT_K + ch * 8 + tt] =
                        __float2bfloat16(acc[nt][j] + ((j >= 2) ? bias_hi : bias_lo));
            }
    }
    __syncthreads();

    // gram: 450 workers = 9 pairs x 25 cells x 2 k-halves (k=64 each)
    if (tid < 450) {
        const int pair = tid / 50, rem = tid % 50;
        const int kh = rem / 25, cell = rem % 25;
        const int v0 = (cell / 5) * 5, w0 = (cell % 5) * 5;
        int br1, gi, gj;
        if (pair < 4) { br1 = 2 * pair;           gi = c_gi9[pair];      gj = c_gj9[pair]; }
        else          { br1 = 8 + 2 * (pair - 4); gi = c_gi1[pair - 4];  gj = c_gj1[pair - 4]; }
        const __nv_bfloat16* f1 = fT + (size_t)(br1 * 25 + v0) * FT_K + kh * 64;
        const __nv_bfloat16* f2 = fT + (size_t)((br1 + 1) * 25 + w0) * FT_K + kh * 64;
        ull g[5][5];
#pragma unroll
        for (int r = 0; r < 5; ++r)
#pragma unroll
            for (int s = 0; s < 5; ++s) g[r][s] = 0ULL;
        for (int kp = 0; kp < 32; ++kp) {
            ull a[5], b[5];
#pragma unroll
            for (int r = 0; r < 5; ++r) {
                float2 fa = __bfloat1622float2(*(const __nv_bfloat162*)(f1 + r * FT_K + kp * 2));
                a[r] = pack2(fa.x, fa.y);
            }
#pragma unroll
            for (int s = 0; s < 5; ++s) {
                float2 fb = __bfloat1622float2(*(const __nv_bfloat162*)(f2 + s * FT_K + kp * 2));
                b[s] = pack2(fb.x, fb.y);
            }
#pragma unroll
            for (int r = 0; r < 5; ++r)
#pragma unroll
                for (int s = 0; s < 5; ++s) fma2(g[r][s], a[r], b[s]);
        }
        float* dst = g_Gram + ((size_t)(n * 3 + gi) * 3 + gj) * 625;
#pragma unroll
        for (int r = 0; r < 5; ++r)
#pragma unroll
            for (int s = 0; s < 5; ++s) {
                float2 f = unpack2(g[r][s]);
                atomicAdd(&dst[(v0 + r) * 25 + (w0 + s)], f.x + f.y);
            }
    }
}

// ---------------- kernel 2: softmax + combine into A1 ----------------------
__global__ void smx_kernel(const float* __restrict__ weights) {
    const int n = blockIdx.x, i = blockIdx.y, w = threadIdx.x;
    if (w >= 25) return;
    const float INV = 1.f / 4096.f / 256.f;   // fp8 x16 scale squared
    const float wj[3] = {weights[5], weights[6], weights[7]};
    float a1[25];
#pragma unroll
    for (int v = 0; v < 25; ++v) a1[v] = g_Acomb[v * 25 + w];
    for (int j = 0; j < 3; ++j) {
        const float* gb = g_Gram + ((size_t)(n * 3 + i) * 3 + j) * 625 + w;
        float m = -1e30f;
        for (int v = 0; v < 25; ++v) m = fmaxf(m, gb[v * 25] * INV);
        float s = 0.f;
        for (int v = 0; v < 25; ++v) s += expf(gb[v * 25] * INV - m);
        float inv = wj[j] / s;
        for (int v = 0; v < 25; ++v) a1[v] += inv * expf(gb[v * 25] * INV - m);
    }
    float* out = g_A1 + (size_t)(n * 3 + i) * 625 + w;
    for (int v = 0; v < 25; ++v) out[v * 25] = a1[v];
}

// ---------------- kernel 3: fin2 (R14-verified) ----------------------------
#define F2_U    0
#define F2_XS   20160
#define F2_A1   26816
#define SMEM_F2 115072

__global__ void __launch_bounds__(512, 2) fin2_kernel(const float* __restrict__ x,
                                                      float* __restrict__ out) {
    extern __shared__ float sm[];
    float* U  = sm + F2_U;          // stride 105
    float* xs = sm + F2_XS;         // stride 104 (104%32=8 -> B-frag bijection)
    ull* A1u  = (ull*)(sm + F2_A1); // [i*25+v][13 wp]
    const int tb = blockIdx.x, nb = blockIdx.y, tid = threadIdx.x;
    const int warp = tid >> 5, lane = tid & 31;

    for (int idx = tid; idx < 64 * 104; idx += 512) {
        int c = idx / 104, j = idx % 104;
        xs[idx] = (j < 100)
            ? tf32r(x[((size_t)(nb * 64 + c)) * 6400 + tb * 100 + j]) : 0.f;
    }
    for (int idx = tid; idx < 975; idx += 512) {
        int wp = idx % 13, r = idx / 13;
        const float* a = g_A1 + (size_t)nb * 1875 + (r / 25) * 625 + (r % 25) * 25;
        float lo = a[2 * wp];
        float hi = (2 * wp + 1 < 25) ? a[2 * wp + 1] : 0.f;
        A1u[idx] = pack2(lo, hi);
    }
    __syncthreads();

    const uint32_t* xsu = (const uint32_t*)xs;
    const float4* AH4 = (const float4*)g_AfH;
    for (int jj = 0; jj < 2; ++jj) {
        if (jj == 1 && warp >= 8) break;
        const int sj = jj ? 16 + warp : warp;
        if (sj >= 24) continue;
        const int strip = sj >> 1, nh = sj & 1;
        const int nt0 = nh * 6;
        float acc[7][4];
#pragma unroll
        for (int a = 0; a < 7; ++a)
#pragma unroll
            for (int b = 0; b < 4; ++b) acc[a][b] = 0.f;
#pragma unroll
        for (int kt = 0; kt < 8; ++kt) {
            float4 ah = AH4[(strip * 8 + kt) * 32 + lane];
            const uint32_t* xb0 = xsu + (8 * kt + (lane & 3)) * 104 + (lane >> 2);
            const uint32_t* xb1 = xb0 + 4 * 104;
#pragma unroll
            for (int nt = 0; nt < 7; ++nt) {
                uint32_t b0 = xb0[(nt0 + nt) * 8];
                uint32_t b1 = xb1[(nt0 + nt) * 8];
                mma_tf32(acc[nt], ah, b0, b1);
            }
        }
        // D-frag store: j&2 -> row+8, j&1 -> col+1 (R7-verified)
#pragma unroll
        for (int nt = 0; nt < 7; ++nt)
#pragma unroll
            for (int j = 0; j < 4; ++j) {
                int r = 16 * strip + (lane >> 2) + ((j & 2) ? 8 : 0);
                int col = (nt0 + nt) * 8 + 2 * (lane & 3) + (j & 1);
                U[r * 105 + col] = acc[nt][j];
            }
    }
    __syncthreads();

    {
        const int t = tid >> 7, o = (tid >> 1) & 63, wh = tid & 1;
        const int wp0 = wh * 6;
        ull acc[7];
#pragma unroll
        for (int wp = 0; wp < 7; ++wp) acc[wp] = 0ULL;
#pragma unroll
        for (int i = 0; i < 3; ++i) {
            const float* Up = U + (i * 64 + o) * 105 + t * 25;
            const ull* Ap = A1u + i * 325;
#pragma unroll
            for (int v = 0; v < 25; ++v) {
                float u = Up[v];
                ull uu = pack2(u, u);
                const ull* a = Ap + v * 13 + wp0;
#pragma unroll
                for (int wp = 0; wp < 7; ++wp) fma2(acc[wp], uu, a[wp]);
            }
        }
        const float bias = g_bd2[o];
        const float* xrow = xs + o * 104 + t * 25;   // residual from smem (tf32 x)
        const size_t base = ((size_t)(nb * 64 + o)) * 6400 + (size_t)(tb * 4 + t) * 25;
#pragma unroll
        for (int wp = 0; wp < 7; ++wp) {
            float2 f = unpack2(acc[wp]);
            int w = 2 * (wp0 + wp);
            out[base + w] = fmaxf(f.x + bias + xrow[w], 0.f);
            if (w + 1 < 25)
                out[base + w + 1] = fmaxf(f.y + bias + xrow[w + 1], 0.f);
        }
    }
}

// ---------------- launch ----------------------------------------------------
extern "C" void kernel_launch(void* const* d_in, const int* in_sizes, int n_in,
                              void* d_out, int out_size) {
    const float* x       = (const float*)d_in[0];
    const float* weights = (const float*)d_in[1];
    const float* A       = (const float*)d_in[2];
    const float* Wa      = (const float*)d_in[3];
    const float* ba      = (const float*)d_in[4];
    const float* Wb      = (const float*)d_in[5];
    const float* bb      = (const float*)d_in[6];
    const float* Wd      = (const float*)d_in[7];
    const float* bd      = (const float*)d_in[8];
    const float* WT1     = (const float*)d_in[9];
    const float* bT1     = (const float*)d_in[10];
    const float* WT2     = (const float*)d_in[11];
    const float* bT2     = (const float*)d_in[12];
    const float* WST11   = (const float*)d_in[13];
    const float* bST11   = (const float*)d_in[14];
    const float* WST12   = (const float*)d_in[15];
    const float* bST12   = (const float*)d_in[16];
    const float* bn_g    = (const float*)d_in[17];
    const float* bn_b    = (const float*)d_in[18];
    const float* bn_m    = (const float*)d_in[19];
    const float* bn_v    = (const float*)d_in[20];
    float* out = (float*)d_out;

    cudaFuncSetAttribute(convm_kernel, cudaFuncAttributeMaxDynamicSharedMemorySize, SMEM_CONV);
    cudaFuncSetAttribute(fin2_kernel,  cudaFuncAttributeMaxDynamicSharedMemorySize, SMEM_F2);

    void* gram_ptr = nullptr;
    cudaGetSymbolAddress(&gram_ptr, g_Gram);

    prepA_kernel<<<1, 640>>>(weights, A, ba, bb, bT1, bT2, bST11, bST12,
                             bd, bn_g, bn_b, bn_m, bn_v);
    prepW_kernel<<<64, 256>>>(Wa, Wb, WT1, WT2, WST11, WST12, Wd, bn_g, bn_v);
    cudaMemsetAsync(gram_ptr, 0, sizeof(float) * 64 * 9 * 625);
    dummy_kernel<<<1, 1>>>();   // shifts ncu's -s 5 -c 1 capture onto convm
    convm_kernel<<<dim3(TT / 8, NB), 512, SMEM_CONV>>>(x);
    smx_kernel<<<dim3(NB, 3), 32>>>(weights);
    fin2_kernel<<<dim3(TT / 4, NB), 512, SMEM_F2>>>(x, out);
}

// round 17
// speedup vs baseline: 2.0629x; 1.1496x over previous
#include <cuda_runtime.h>
#include <cuda_bf16.h>
#include <cstdint>

#define NB   64
#define CC   64
#define TT   256
#define VV   25

typedef unsigned long long ull;

// ---------------- scratch (static device memory) ----------------
__device__ __align__(16) uint4 g_W9f[9 * 8 * 2 * 32];
__device__ __align__(16) uint4 g_W1f[10 * 2 * 32];
__device__ float g_b9[128];                            // x16
__device__ float g_b1[160];                            // x16
__device__ float g_Acomb[625];
__device__ float g_Gram[64 * 9 * 625];                 // x256
__device__ float g_A1[64 * 3 * 625];
__device__ __align__(16) float g_AfH[12288];
__device__ float g_bd2[64];

// branch tables
__constant__ int c_i9[8]  = {0,0,1,1,1,1,2,2};
__constant__ int c_s9[8]  = {0,1,0,1,2,3,0,1};
__constant__ int c_i1[10] = {0,0,0,0,1,1,2,2,2,2};
__constant__ int c_s1[10] = {0,1,2,3,0,1,0,1,2,3};
__constant__ int c_gi9[4] = {0,1,1,2};
__constant__ int c_gj9[4] = {1,1,2,1};
__constant__ int c_gi1[5] = {0,0,1,2,2};
__constant__ int c_gj1[5] = {0,2,0,0,2};

// ---------------- helpers ----------------
__device__ __forceinline__ ull pack2(float lo, float hi) {
    ull r; asm("mov.b64 %0, {%1,%2};" : "=l"(r) : "f"(lo), "f"(hi)); return r;
}
__device__ __forceinline__ void fma2(ull& d, ull a, ull b) {
    asm("fma.rn.f32x2 %0, %1, %2, %0;" : "+l"(d) : "l"(a), "l"(b));
}
__device__ __forceinline__ float2 unpack2(ull p) {
    float2 f; asm("mov.b64 {%0,%1}, %2;" : "=f"(f.x), "=f"(f.y) : "l"(p)); return f;
}
__device__ __forceinline__ float tf32r(float f) {
    uint32_t u;
    asm("cvt.rn.tf32.f32 %0, %1;" : "=r"(u) : "f"(f));
    return __uint_as_float(u);
}
__device__ __forceinline__ uint16_t f2e4m3x2(float hi, float lo) {
    uint16_t u;
    asm("cvt.rn.satfinite.e4m3x2.f32 %0, %1, %2;" : "=h"(u) : "f"(hi), "f"(lo));
    return u;
}
__device__ __forceinline__ void mma_e4m3(float* d, uint32_t a0, uint32_t a1,
                                         uint32_t a2, uint32_t a3,
                                         uint32_t b0, uint32_t b1) {
    asm volatile(
        "mma.sync.aligned.m16n8k32.row.col.f32.e4m3.e4m3.f32 "
        "{%0,%1,%2,%3}, {%4,%5,%6,%7}, {%8,%9}, {%0,%1,%2,%3};"
        : "+f"(d[0]), "+f"(d[1]), "+f"(d[2]), "+f"(d[3])
        : "r"(a0), "r"(a1), "r"(a2), "r"(a3), "r"(b0), "r"(b1));
}
__device__ __forceinline__ void mma_bf16(float* d, uint32_t a0, uint32_t a1,
                                         uint32_t a2, uint32_t a3,
                                         uint32_t b0, uint32_t b1) {
    asm volatile(
        "mma.sync.aligned.m16n8k16.row.col.f32.bf16.bf16.f32 "
        "{%0,%1,%2,%3}, {%4,%5,%6,%7}, {%8,%9}, {%0,%1,%2,%3};"
        : "+f"(d[0]), "+f"(d[1]), "+f"(d[2]), "+f"(d[3])
        : "r"(a0), "r"(a1), "r"(a2), "r"(a3), "r"(b0), "r"(b1));
}
__device__ __forceinline__ void mma_tf32(float* d, float4 a, uint32_t b0, uint32_t b1) {
    asm volatile(
        "mma.sync.aligned.m16n8k8.row.col.f32.tf32.tf32.f32 "
        "{%0,%1,%2,%3}, {%4,%5,%6,%7}, {%8,%9}, {%0,%1,%2,%3};"
        : "+f"(d[0]), "+f"(d[1]), "+f"(d[2]), "+f"(d[3])
        : "r"(__float_as_uint(a.x)), "r"(__float_as_uint(a.y)),
          "r"(__float_as_uint(a.z)), "r"(__float_as_uint(a.w)),
          "r"(b0), "r"(b1));
}

// ---------------- kernel 0a: prepA ----------------
__global__ void prepA_kernel(const float* __restrict__ weights, const float* __restrict__ A,
                             const float* __restrict__ ba, const float* __restrict__ bb,
                             const float* __restrict__ bT1, const float* __restrict__ bT2,
                             const float* __restrict__ bST11, const float* __restrict__ bST12,
                             const float* __restrict__ bd,
                             const float* __restrict__ gamma, const float* __restrict__ beta,
                             const float* __restrict__ mean, const float* __restrict__ var) {
    __shared__ float sA[625], sA4[625];
    const int tid = threadIdx.x;
    if (tid < 625) {
        float a = A[tid];
        sA[tid] = a;
        int v = tid / 25, w = tid % 25;
        float a2 = a * a;  // elementwise Chebyshev (torch.pow semantics)
        sA4[tid] = 8.f * a2 * a2 - 8.f * a2 + (v == w ? 1.f : 0.f);
    }
    __syncthreads();
    if (tid < 25) {
        const int w = tid;
        float w0 = weights[0], w1 = weights[1];
        float m = -1e30f;
        for (int v = 0; v < 25; ++v) m = fmaxf(m, sA4[v*25+w] * 0.04f);
        float ssum = 0.f;
        for (int v = 0; v < 25; ++v) ssum += expf(sA4[v*25+w] * 0.04f - m);
        float inv = 1.f / ssum;
        for (int v = 0; v < 25; ++v)
            g_Acomb[v*25+w] = w0 * sA[v*25+w] + w1 * expf(sA4[v*25+w] * 0.04f - m) * inv;
    }
    for (int idx = tid; idx < 128; idx += blockDim.x) {
        int g = idx >> 4, c = idx & 15;
        int i = c_i9[g], s = c_s9[g];
        const float* B = (s == 0) ? bT1 : (s == 1) ? bT2 : (s == 2) ? bST11 : bST12;
        g_b9[idx] = 16.f * B[i*16 + c];
    }
    for (int idx = tid; idx < 160; idx += blockDim.x) {
        int g = idx >> 4, c = idx & 15;
        int i = c_i1[g], s = c_s1[g];
        const float* B = (s == 0) ? ba : (s == 1) ? bb : (s == 2) ? bST11 : bST12;
        g_b1[idx] = 16.f * B[i*16 + c];
    }
    for (int o = tid; o < 64; o += blockDim.x) {
        float sc = gamma[o] * rsqrtf(var[o] + 1e-5f);
        g_bd2[o] = (bd[o] + bd[64 + o] + bd[128 + o] - mean[o]) * sc + beta[o];
    }
}

// ---------------- kernel 0b: prepW ----------------
__global__ void prepW_kernel(const float* __restrict__ Wa, const float* __restrict__ Wb,
                             const float* __restrict__ WT1, const float* __restrict__ WT2,
                             const float* __restrict__ WST11, const float* __restrict__ WST12,
                             const float* __restrict__ Wd,
                             const float* __restrict__ gamma, const float* __restrict__ var) {
    const int gtid = blockIdx.x * blockDim.x + threadIdx.x;
    const int gsz = gridDim.x * blockDim.x;
    for (int idx = gtid; idx < 9 * 8 * 2 * 32 * 4; idx += gsz) {
        int j = idx & 3, lane = (idx >> 2) & 31, k0i = (idx >> 7) & 1;
        int strip = (idx >> 8) & 7, tap = idx >> 11;
        int row = lane >> 2, kq4 = (lane & 3) * 4;
        int ch = strip * 16 + row + ((j & 1) ? 8 : 0);
        int cin0 = k0i * 32 + kq4 + ((j & 2) ? 16 : 0);
        int g = ch >> 4;
        int i = c_i9[g], s = c_s9[g];
        const float* W = (s == 0) ? WT1 : (s == 1) ? WT2 : (s == 2) ? WST11 : WST12;
        const float* base = W + ((size_t)(i*16 + (ch & 15))*64 + cin0) * 9 + tap;
        uint32_t lo = f2e4m3x2(16.f * base[9],  16.f * base[0]);
        uint32_t hi = f2e4m3x2(16.f * base[27], 16.f * base[18]);
        ((uint32_t*)g_W9f)[idx] = lo | (hi << 16);
    }
    for (int idx = gtid; idx < 10 * 2 * 32 * 4; idx += gsz) {
        int j = idx & 3, lane = (idx >> 2) & 31, k0i = (idx >> 7) & 1;
        int strip = idx >> 8;
        int row = lane >> 2, kq4 = (lane & 3) * 4;
        int ch = strip * 16 + row + ((j & 1) ? 8 : 0);
        int cin0 = k0i * 32 + kq4 + ((j & 2) ? 16 : 0);
        int g = ch >> 4;
        int i = c_i1[g], s = c_s1[g];
        float w[4];
#pragma unroll
        for (int b = 0; b < 4; ++b) {
            int cin = cin0 + b;
            if (s == 0)      w[b] = Wa[(i*16 + (ch & 15))*64 + cin];
            else if (s == 1) w[b] = Wb[(i*16 + (ch & 15))*64 + cin];
            else if (s == 2) w[b] = WST11[((i*16 + (ch & 15))*64 + cin)*9 + 4];
            else             w[b] = WST12[((i*16 + (ch & 15))*64 + cin)*9 + 4];
        }
        uint32_t lo = f2e4m3x2(16.f * w[1], 16.f * w[0]);
        uint32_t hi = f2e4m3x2(16.f * w[3], 16.f * w[2]);
        ((uint32_t*)g_W1f)[idx] = lo | (hi << 16);
    }
    // A-frag (R7-verified): j&1 -> row+8, j&2 -> col+4
    for (int idx = gtid; idx < 12288; idx += gsz) {
        int j = idx & 3, lane = (idx >> 2) & 31, kt = (idx >> 7) & 7, s = idx >> 10;
        int row = (lane >> 2) + ((j & 1) ? 8 : 0);
        int col = (lane & 3) + ((j & 2) ? 4 : 0);
        int m = 16 * s + row, c = 8 * kt + col;
        int i = m >> 6, o = m & 63;
        float sc = gamma[o] * rsqrtf(var[o] + 1e-5f);
        g_AfH[idx] = tf32r(Wd[(i * 64 + o) * 64 + c] * sc);
    }
}

// ---------------- dummy (shifts ncu -s 5 capture onto convm) ---------------
__global__ void dummy_kernel() {}

// ---------------- kernel 1: unified conv (fp8 mma, 8t) + mma gram ----------
// xs: fp8 [512 rows][144B]; fT: bf16 [458 rows][136] (18*25 valid + slack)
#define XS_ROW_B    144
#define XS_BYTES    (512 * XS_ROW_B)            // 73728
#define FT_K        136
#define FT_ROWS     458
#define SMEM_CONV   (XS_BYTES + FT_ROWS * FT_K * 2)   // 198304 B

__global__ void __launch_bounds__(512, 1) convm_kernel(const float* __restrict__ x) {
    extern __shared__ uint8_t smu[];
    uint8_t* xs = smu;
    __nv_bfloat16* fT = (__nv_bfloat16*)(smu + XS_BYTES);
    const int n = blockIdx.y, t0 = blockIdx.x * 8;
    const int tid = threadIdx.x, warp = tid >> 5, lane = tid & 31;

    // stage x -> e4m3, 2 cin per u16 store
    {
        const float* xn = x + (size_t)n * (CC * TT * VV);
        for (int idx = tid; idx < 32 * 16 * 25; idx += 512) {
            int cinp = idx / 400, r = idx % 400;
            int tsl = r / 25, v = r % 25;
            int t = t0 - 4 + tsl;
            float v0 = 0.f, v1 = 0.f;
            if (t >= 0 && t < TT) {
                const float* p = xn + ((size_t)(2 * cinp) * TT + t) * VV + v;
                v0 = p[0];
                v1 = p[TT * VV];
            }
            *(uint16_t*)(xs + (tsl * 32 + v) * XS_ROW_B + 2 * cinp) = f2e4m3x2(v1, v0);
        }
    }
    __syncthreads();

    const int row = lane >> 2;
    float acc[16][4];

    for (int ph = 0; ph < 3; ++ph) {
        if (ph == 2 && warp >= 4) break;
        int strip, half, is9;
        if (ph == 0) { strip = warp >> 1; half = warp & 1; is9 = 1; }
        else {
            int c1 = (ph == 1) ? warp : 16 + warp;
            strip = c1 >> 1; half = c1 & 1; is9 = 0;
        }
#pragma unroll
        for (int a = 0; a < 16; ++a)
#pragma unroll
            for (int b = 0; b < 4; ++b) acc[a][b] = 0.f;

        const int kq4 = (lane & 3) * 4;
        const int ntaps = is9 ? 9 : 1;
        for (int jt = 0; jt < ntaps; ++jt) {
            const int tap = is9 ? jt : 4;
            const uint4* Af = is9 ? g_W9f + (size_t)((tap * 8 + strip) * 2) * 32
                                  : g_W1f + (size_t)(strip * 2) * 32;
            const uint8_t* xb = xs + (size_t)(tap * 32 + half * 128 + row) * XS_ROW_B;
#pragma unroll
            for (int k0i = 0; k0i < 2; ++k0i) {
                const uint4 af = Af[k0i * 32 + lane];
                const int k0 = k0i * 32;
#pragma unroll
                for (int nt = 0; nt < 16; ++nt) {
                    uint32_t b0 = *(const uint32_t*)(xb + nt * 8 * XS_ROW_B + k0 + kq4);
                    uint32_t b1 = *(const uint32_t*)(xb + nt * 8 * XS_ROW_B + k0 + kq4 + 16);
                    mma_e4m3(acc[nt], af.x, af.y, af.z, af.w, b0, b1);
                }
            }
        }
        const int fstrip = is9 ? strip : 8 + strip;
        const float* bias_arr = is9 ? g_b9 + strip * 16 : g_b1 + strip * 16;
        const float bias_lo = bias_arr[row];
        const float bias_hi = bias_arr[row + 8];
#pragma unroll
        for (int nt = 0; nt < 16; ++nt)
#pragma unroll
            for (int j = 0; j < 4; ++j) {
                const int ch = row + ((j >= 2) ? 8 : 0);
                const int nl = half * 128 + nt * 8 + (lane & 3) * 2 + (j & 1);
                const int tt = nl >> 5, v = nl & 31;
                if (v < 25)
                    fT[(fstrip * 25 + v) * FT_K + ch * 8 + tt] =
                        __float2bfloat16(acc[nt][j] + ((j >= 2) ? bias_hi : bias_lo));
            }
    }
    __syncthreads();

    // gram via bf16 mma: 18 jobs = 9 pairs x 2 M16-tiles; 4 N8-tiles per job.
    // Out-of-tile rows (v,w >= 25) produce garbage discarded by the predicate.
    for (int jr = 0; jr < 2; ++jr) {
        const int job = jr ? 16 + warp : warp;
        if (job >= 18) break;
        const int pair = job >> 1, mt = job & 1;
        int br1, gi, gj;
        if (pair < 4) { br1 = 2 * pair;           gi = c_gi9[pair];      gj = c_gj9[pair]; }
        else          { br1 = 8 + 2 * (pair - 4); gi = c_gi1[pair - 4];  gj = c_gj1[pair - 4]; }
        const __nv_bfloat16* f1 = fT + (size_t)(br1 * 25 + mt * 16) * FT_K;
        const __nv_bfloat16* f2 = fT + (size_t)((br1 + 1) * 25) * FT_K;
        float g[4][4];
#pragma unroll
        for (int a = 0; a < 4; ++a)
#pragma unroll
            for (int b = 0; b < 4; ++b) g[a][b] = 0.f;
#pragma unroll
        for (int ks = 0; ks < 8; ++ks) {
            const int kc = ks * 16 + (lane & 3) * 2;
            uint32_t a0 = *(const uint32_t*)(f1 + row * FT_K + kc);
            uint32_t a1 = *(const uint32_t*)(f1 + (row + 8) * FT_K + kc);
            uint32_t a2 = *(const uint32_t*)(f1 + row * FT_K + kc + 8);
            uint32_t a3 = *(const uint32_t*)(f1 + (row + 8) * FT_K + kc + 8);
#pragma unroll
            for (int ntile = 0; ntile < 4; ++ntile) {
                uint32_t b0 = *(const uint32_t*)(f2 + (ntile * 8 + row) * FT_K + kc);
                uint32_t b1 = *(const uint32_t*)(f2 + (ntile * 8 + row) * FT_K + kc + 8);
                mma_bf16(g[ntile], a0, a1, a2, a3, b0, b1);
            }
        }
        float* dst = g_Gram + ((size_t)(n * 3 + gi) * 3 + gj) * 625;
#pragma unroll
        for (int ntile = 0; ntile < 4; ++ntile)
#pragma unroll
            for (int j = 0; j < 4; ++j) {
                int v = mt * 16 + row + ((j & 2) ? 8 : 0);
                int w = ntile * 8 + 2 * (lane & 3) + (j & 1);
                if (v < 25 && w < 25)
                    atomicAdd(&dst[v * 25 + w], g[ntile][j]);
            }
    }
}

// ---------------- kernel 2: softmax + combine into A1 ----------------------
__global__ void smx_kernel(const float* __restrict__ weights) {
    const int n = blockIdx.x, i = blockIdx.y, w = threadIdx.x;
    if (w >= 25) return;
    const float INV = 1.f / 4096.f / 256.f;   // fp8 x16 scale squared
    const float wj[3] = {weights[5], weights[6], weights[7]};
    float a1[25];
#pragma unroll
    for (int v = 0; v < 25; ++v) a1[v] = g_Acomb[v * 25 + w];
    for (int j = 0; j < 3; ++j) {
        const float* gb = g_Gram + ((size_t)(n * 3 + i) * 3 + j) * 625 + w;
        float m = -1e30f;
        for (int v = 0; v < 25; ++v) m = fmaxf(m, gb[v * 25] * INV);
        float s = 0.f;
        for (int v = 0; v < 25; ++v) s += expf(gb[v * 25] * INV - m);
        float inv = wj[j] / s;
        for (int v = 0; v < 25; ++v) a1[v] += inv * expf(gb[v * 25] * INV - m);
    }
    float* out = g_A1 + (size_t)(n * 3 + i) * 625 + w;
    for (int v = 0; v < 25; ++v) out[v * 25] = a1[v];
}

// ---------------- kernel 3: fin2 (R14-verified) ----------------------------
#define F2_U    0
#define F2_XS   20160
#define F2_A1   26816
#define SMEM_F2 115072

__global__ void __launch_bounds__(512, 2) fin2_kernel(const float* __restrict__ x,
                                                      float* __restrict__ out) {
    extern __shared__ float sm[];
    float* U  = sm + F2_U;          // stride 105
    float* xs = sm + F2_XS;         // stride 104
    ull* A1u  = (ull*)(sm + F2_A1);
    const int tb = blockIdx.x, nb = blockIdx.y, tid = threadIdx.x;
    const int warp = tid >> 5, lane = tid & 31;

    for (int idx = tid; idx < 64 * 104; idx += 512) {
        int c = idx / 104, j = idx % 104;
        xs[idx] = (j < 100)
            ? tf32r(x[((size_t)(nb * 64 + c)) * 6400 + tb * 100 + j]) : 0.f;
    }
    for (int idx = tid; idx < 975; idx += 512) {
        int wp = idx % 13, r = idx / 13;
        const float* a = g_A1 + (size_t)nb * 1875 + (r / 25) * 625 + (r % 25) * 25;
        float lo = a[2 * wp];
        float hi = (2 * wp + 1 < 25) ? a[2 * wp + 1] : 0.f;
        A1u[idx] = pack2(lo, hi);
    }
    __syncthreads();

    const uint32_t* xsu = (const uint32_t*)xs;
    const float4* AH4 = (const float4*)g_AfH;
    for (int jj = 0; jj < 2; ++jj) {
        if (jj == 1 && warp >= 8) break;
        const int sj = jj ? 16 + warp : warp;
        if (sj >= 24) continue;
        const int strip = sj >> 1, nh = sj & 1;
        const int nt0 = nh * 6;
        float acc[7][4];
#pragma unroll
        for (int a = 0; a < 7; ++a)
#pragma unroll
            for (int b = 0; b < 4; ++b) acc[a][b] = 0.f;
#pragma unroll
        for (int kt = 0; kt < 8; ++kt) {
            float4 ah = AH4[(strip * 8 + kt) * 32 + lane];
            const uint32_t* xb0 = xsu + (8 * kt + (lane & 3)) * 104 + (lane >> 2);
            const uint32_t* xb1 = xb0 + 4 * 104;
#pragma unroll
            for (int nt = 0; nt < 7; ++nt) {
                uint32_t b0 = xb0[(nt0 + nt) * 8];
                uint32_t b1 = xb1[(nt0 + nt) * 8];
                mma_tf32(acc[nt], ah, b0, b1);
            }
        }
        // D-frag store: j&2 -> row+8, j&1 -> col+1 (R7-verified)
#pragma unroll
        for (int nt = 0; nt < 7; ++nt)
#pragma unroll
            for (int j = 0; j < 4; ++j) {
                int r = 16 * strip + (lane >> 2) + ((j & 2) ? 8 : 0);
                int col = (nt0 + nt) * 8 + 2 * (lane & 3) + (j & 1);
                U[r * 105 + col] = acc[nt][j];
            }
    }
    __syncthreads();

    {
        const int t = tid >> 7, o = (tid >> 1) & 63, wh = tid & 1;
        const int wp0 = wh * 6;
        ull acc[7];
#pragma unroll
        for (int wp = 0; wp < 7; ++wp) acc[wp] = 0ULL;
#pragma unroll
        for (int i = 0; i < 3; ++i) {
            const float* Up = U + (i * 64 + o) * 105 + t * 25;
            const ull* Ap = A1u + i * 325;
#pragma unroll
            for (int v = 0; v < 25; ++v) {
                float u = Up[v];
                ull uu = pack2(u, u);
                const ull* a = Ap + v * 13 + wp0;
#pragma unroll
                for (int wp = 0; wp < 7; ++wp) fma2(acc[wp], uu, a[wp]);
            }
        }
        const float bias = g_bd2[o];
        const float* xrow = xs + o * 104 + t * 25;
        const size_t base = ((size_t)(nb * 64 + o)) * 6400 + (size_t)(tb * 4 + t) * 25;
#pragma unroll
        for (int wp = 0; wp < 7; ++wp) {
            float2 f = unpack2(acc[wp]);
            int w = 2 * (wp0 + wp);
            out[base + w] = fmaxf(f.x + bias + xrow[w], 0.f);
            if (w + 1 < 25)
                out[base + w + 1] = fmaxf(f.y + bias + xrow[w + 1], 0.f);
        }
    }
}

// ---------------- launch ----------------------------------------------------
extern "C" void kernel_launch(void* const* d_in, const int* in_sizes, int n_in,
                              void* d_out, int out_size) {
    const float* x       = (const float*)d_in[0];
    const float* weights = (const float*)d_in[1];
    const float* A       = (const float*)d_in[2];
    const float* Wa      = (const float*)d_in[3];
    const float* ba      = (const float*)d_in[4];
    const float* Wb      = (const float*)d_in[5];
    const float* bb      = (const float*)d_in[6];
    const float* Wd      = (const float*)d_in[7];
    const float* bd      = (const float*)d_in[8];
    const float* WT1     = (const float*)d_in[9];
    const float* bT1     = (const float*)d_in[10];
    const float* WT2     = (const float*)d_in[11];
    const float* bT2     = (const float*)d_in[12];
    const float* WST11   = (const float*)d_in[13];
    const float* bST11   = (const float*)d_in[14];
    const float* WST12   = (const float*)d_in[15];
    const float* bST12   = (const float*)d_in[16];
    const float* bn_g    = (const float*)d_in[17];
    const float* bn_b    = (const float*)d_in[18];
    const float* bn_m    = (const float*)d_in[19];
    const float* bn_v    = (const float*)d_in[20];
    float* out = (float*)d_out;

    cudaFuncSetAttribute(convm_kernel, cudaFuncAttributeMaxDynamicSharedMemorySize, SMEM_CONV);
    cudaFuncSetAttribute(fin2_kernel,  cudaFuncAttributeMaxDynamicSharedMemorySize, SMEM_F2);

    void* gram_ptr = nullptr;
    cudaGetSymbolAddress(&gram_ptr, g_Gram);

    prepA_kernel<<<1, 640>>>(weights, A, ba, bb, bT1, bT2, bST11, bST12,
                             bd, bn_g, bn_b, bn_m, bn_v);
    prepW_kernel<<<64, 256>>>(Wa, Wb, WT1, WT2, WST11, WST12, Wd, bn_g, bn_v);
    cudaMemsetAsync(gram_ptr, 0, sizeof(float) * 64 * 9 * 625);
    dummy_kernel<<<1, 1>>>();   // keeps ncu's -s 5 -c 1 capture on convm
    convm_kernel<<<dim3(TT / 8, NB), 512, SMEM_CONV>>>(x);
    smx_kernel<<<dim3(NB, 3), 32>>>(weights);
    fin2_kernel<<<dim3(TT / 4, NB), 512, SMEM_F2>>>(x, out);
}